// round 12
// baseline (speedup 1.0000x reference)
#include <cuda_runtime.h>
#include <cuda_bf16.h>
#include <cstdint>

#define N_NODES 100000
#define N_EDGES 640000
#define FEAT 128
#define HID 256
#define NCLS 10

// ---------------------------------------------------------------------------
// Persistent scratch (re-initialized every launch before use).
// ---------------------------------------------------------------------------
__device__ __align__(16) float g_h1[N_NODES * HID];
__device__ __align__(16) float g_h[N_NODES * HID];
__device__ __align__(16) float g_z[N_NODES * HID];
__device__ int g_src[N_EDGES];
__device__ int g_dst[N_EDGES];
__device__ int g_ssrc[N_EDGES];     // src sorted by dst
__device__ int g_cnt[N_NODES];
__device__ int g_off[N_NODES + 1];
__device__ int g_cur[N_NODES];
__device__ int g_bsum[128];         // scan block sums
// prepped weights, bf16: [chunk][plane(hi,lo)][k(32)][n(256)]
__device__ __align__(16) __nv_bfloat16 g_wp1[4 * 2 * 32 * 256];  // W1a K=128
__device__ __align__(16) __nv_bfloat16 g_wp2[8 * 2 * 32 * 256];  // W1b K=256
__device__ __align__(16) __nv_bfloat16 g_wp3[8 * 2 * 32 * 256];  // W2a K=256

// ---------------------------------------------------------------------------
// mma.sync helpers (legacy tensor-core path; valid at compute_100)
// ---------------------------------------------------------------------------
#define LDSM4(r, a)                                                           \
    asm volatile("ldmatrix.sync.aligned.m8n8.x4.shared.b16 {%0,%1,%2,%3}, [%4];" \
                 : "=r"((r)[0]), "=r"((r)[1]), "=r"((r)[2]), "=r"((r)[3])     \
                 : "r"(a))
#define LDSM2T(r, a)                                                          \
    asm volatile("ldmatrix.sync.aligned.m8n8.x2.trans.shared.b16 {%0,%1}, [%2];" \
                 : "=r"((r)[0]), "=r"((r)[1])                                 \
                 : "r"(a))
#define MMA16816(c, A, B)                                                     \
    asm volatile(                                                             \
        "mma.sync.aligned.m16n8k16.row.col.f32.bf16.bf16.f32 "                \
        "{%0,%1,%2,%3},{%4,%5,%6,%7},{%8,%9},{%0,%1,%2,%3};"                  \
        : "+f"((c)[0]), "+f"((c)[1]), "+f"((c)[2]), "+f"((c)[3])              \
        : "r"((A)[0]), "r"((A)[1]), "r"((A)[2]), "r"((A)[3]), "r"((B)[0]),    \
          "r"((B)[1]))
#define CP_ASYNC16(dst, src)                                                  \
    asm volatile("cp.async.cg.shared.global [%0], [%1], 16;" ::"r"(dst),      \
                 "l"(src) : "memory")
#define CP_COMMIT() asm volatile("cp.async.commit_group;" ::: "memory")
#define CP_WAIT0() asm volatile("cp.async.wait_group 0;" ::: "memory")

__device__ __forceinline__ uint32_t smem_u32(const void* p) {
    uint32_t a;
    asm("{ .reg .u64 t; cvta.to.shared.u64 t, %1; cvt.u32.u64 %0, t; }"
        : "=r"(a) : "l"(p));
    return a;
}
// pack two floats to bf16x2 (lo -> low 16 bits)
__device__ __forceinline__ uint32_t pk(float lo, float hi) {
    uint32_t r;
    asm("cvt.rn.bf16x2.f32 %0, %1, %2;" : "=r"(r) : "f"(hi), "f"(lo));
    return r;
}
__device__ __forceinline__ float bfr(float x) {
    return __bfloat162float(__float2bfloat16(x));
}

// ---------------------------------------------------------------------------
// Fused setup: weight prep (3 matrices) + zero histogram bins.
// Weight layout: [chunk(K/32)][plane(hi,lo)][k(32)][n(256)]
// ---------------------------------------------------------------------------
__device__ __forceinline__ void prep_one(const float* __restrict__ W,
                                         __nv_bfloat16* __restrict__ out,
                                         int i) {
    int k = i >> 8;
    int n = i & 255;
    float v = W[(size_t)k * 256 + n];
    __nv_bfloat16 hi = __float2bfloat16(v);
    __nv_bfloat16 lo = __float2bfloat16(v - __bfloat162float(hi));
    int chunk = k >> 5, kk = k & 31;
    size_t base = ((size_t)chunk * 2 * 32 + kk) * 256 + n;
    out[base] = hi;
    out[base + (size_t)32 * 256] = lo;
}

__global__ void setup_kernel(const float* __restrict__ W1a,
                             const float* __restrict__ W1b,
                             const float* __restrict__ W2a,
                             __nv_bfloat16* __restrict__ wp1,
                             __nv_bfloat16* __restrict__ wp2,
                             __nv_bfloat16* __restrict__ wp3) {
    int i = blockIdx.x * 256 + threadIdx.x;
    if (i < 128 * 256) prep_one(W1a, wp1, i);
    if (i < 256 * 256) {
        prep_one(W1b, wp2, i);
        prep_one(W2a, wp3, i);
    }
    if (i < N_NODES) g_cnt[i] = 0;
}

// ---------------------------------------------------------------------------
// Edge-index conversion + histogram with per-block dtype sniff (JAX may
// demote int64->int32): genuine int64 of values < 2^31 has 0 in every odd
// 32-bit word of the first 256 slots; int32 random data cannot (p~1e-1280).
// ---------------------------------------------------------------------------
__global__ void convert_hist_kernel(const void* __restrict__ ei) {
    __shared__ int s_is64;
    if (threadIdx.x == 0) {
        const unsigned int* w = (const unsigned int*)ei;
        int is64 = 1;
        for (int i = 0; i < 256; i++)
            if (w[2 * i + 1] != 0u) { is64 = 0; break; }
        s_is64 = is64;
    }
    __syncthreads();
    int e = blockIdx.x * 256 + threadIdx.x;
    if (e >= N_EDGES) return;
    int s, d;
    if (s_is64) {
        const long long* p = (const long long*)ei;
        s = (int)p[e];
        d = (int)p[N_EDGES + e];
    } else {
        const int* p = (const int*)ei;
        s = p[e];
        d = p[N_EDGES + e];
    }
    s = min(max(s, 0), N_NODES - 1);
    d = min(max(d, 0), N_NODES - 1);
    g_src[e] = s;
    g_dst[e] = d;
    atomicAdd(&g_cnt[d], 1);
}

// scan step 1: per-block (1024 elems) exclusive scan + block sums
__global__ void scan1_kernel() {
    __shared__ int sh[1024];
    const int tid = threadIdx.x;
    int i = blockIdx.x * 1024 + tid;
    int v = (i < N_NODES) ? g_cnt[i] : 0;
    sh[tid] = v;
    __syncthreads();
#pragma unroll
    for (int o = 1; o < 1024; o <<= 1) {
        int t = (tid >= o) ? sh[tid - o] : 0;
        __syncthreads();
        sh[tid] += t;
        __syncthreads();
    }
    if (i < N_NODES) g_off[i] = sh[tid] - v;
    if (tid == 1023) g_bsum[blockIdx.x] = sh[1023];
}

// scan step 2: exclusive scan over block sums (<=128 entries), one block
__global__ void scan2_kernel(int nb) {
    __shared__ int sh[128];
    const int tid = threadIdx.x;
    int v = (tid < nb) ? g_bsum[tid] : 0;
    sh[tid] = v;
    __syncthreads();
#pragma unroll
    for (int o = 1; o < 128; o <<= 1) {
        int t = (tid >= o) ? sh[tid - o] : 0;
        __syncthreads();
        sh[tid] += t;
        __syncthreads();
    }
    if (tid < nb) g_bsum[tid] = sh[tid] - v;
}

// scan step 3: add block prefix, init cursors, cap sentinel
__global__ void scan3_kernel() {
    int i = blockIdx.x * 1024 + threadIdx.x;
    if (i < N_NODES) {
        int v = g_off[i] + g_bsum[blockIdx.x];
        g_off[i] = v;
        g_cur[i] = v;
    }
    if (i == 0) g_off[N_NODES] = N_EDGES;
}

__global__ void scatter_kernel() {
    int e = blockIdx.x * 256 + threadIdx.x;
    if (e >= N_EDGES) return;
    int d = g_dst[e];
    int pos = atomicAdd(&g_cur[d], 1);
    g_ssrc[pos] = g_src[e];
}

// ---------------------------------------------------------------------------
// bf16x3 mma.sync GEMM, full-width tile: C[M,256] = relu(A[M,K]@W[K,256]+b)
// CTA 128x256, 512 threads (16 warps 4m x 4n), warp tile 32x64, BK=32,
// 2 stages. SMEM/stage: A_hi[128][40bf16] | A_lo | B_hi[32][264bf16] | B_lo
// FUSED variant: A rows built on the fly as x[node] + sum_{j->node} x[src_j]
// (GIN aggregation folded into the A-path; agg buffers eliminated).
// ---------------------------------------------------------------------------
#define A_HI_OFF 0
#define A_LO_OFF 10240
#define B_HI_OFF 20480
#define B_LO_OFF 37376                 // B_HI + 32*528
#define STAGE_BYTES 54272              // B_LO + 32*528
#define SMEM_MMA_BYTES (2 * STAGE_BYTES)

template <int NC, bool FUSED>  // NC = K/32
__global__ __launch_bounds__(512)
void gemm_mma(const float* __restrict__ A,
              const __nv_bfloat16* __restrict__ wp,
              const float* __restrict__ bias, float* __restrict__ C, int M) {
    extern __shared__ __align__(1024) char smem[];
    const uint32_t sb = smem_u32(smem);
    const int K = NC * 32;
    const int C4 = NC * 8;  // float4 per row
    const int t = threadIdx.x;
    const int lane = t & 31;
    const int warp = t >> 5;
    const int warp_m = warp >> 2;  // 0..3 (32 rows each)
    const int warp_n = warp & 3;   // 0..3 (64 cols each)
    const int bm = blockIdx.x * 128;

    // ---- A fill coords: thread -> (row 0..127, q = 8-float segment) ----
    const int a_row = t >> 2;
    const int a_q = t & 3;
    const int node = bm + a_row;
    const bool rok = node < M;
    const float* Ag = A + (size_t)node * K + a_q * 8;
    const float4* x4 = reinterpret_cast<const float4*>(A);
    const uint32_t a_dst = sb + a_row * 80 + a_q * 16;
    int e0 = 0, e1 = 0;
    if (FUSED && rok) {
        e0 = g_off[node];
        e1 = g_off[node + 1];
    }

    // ---- ldmatrix per-thread offsets ----
    const int lm_arow = warp_m * 32 + (lane & 7) + ((lane >> 3) & 1) * 8;
    const uint32_t a_lm = sb + lm_arow * 80 + ((lane >> 4) & 1) * 16;
    const uint32_t b_lm = sb + B_HI_OFF + (lane & 15) * 528 + warp_n * 128;

    float acc[2][8][4];
#pragma unroll
    for (int i = 0; i < 2; i++)
#pragma unroll
        for (int j = 0; j < 8; j++)
#pragma unroll
            for (int k = 0; k < 4; k++) acc[i][j][k] = 0.f;

    // ---- helpers ----
    auto fill_B = [&](int c, int stg) {
        // 2 planes x 32 k-rows x 512B = 2048 x 16B chunks; 4 per thread
#pragma unroll
        for (int i = 0; i < 4; i++) {
            int f = t + i * 512;
            int pl = f >> 10;
            int k = (f >> 5) & 31;
            int seg = f & 31;
            const __nv_bfloat16* src =
                wp + (((size_t)c * 2 + pl) * 32 + k) * 256 + seg * 8;
            uint32_t dst = sb + stg * STAGE_BYTES +
                           (pl ? B_LO_OFF : B_HI_OFF) + k * 528 + seg * 16;
            CP_ASYNC16(dst, (const void*)src);
        }
        CP_COMMIT();
    };
    auto load_A = [&](int c, float4& v0, float4& v1) {
        if (!rok) {
            v0 = make_float4(0.f, 0.f, 0.f, 0.f);
            v1 = v0;
            return;
        }
        if (FUSED) {
            const float4* bp = x4 + (size_t)node * C4 + c * 8 + a_q * 2;
            v0 = bp[0];
            v1 = bp[1];
            int e = e0;
            // 2-wide batches: 4 independent loads in flight per step
            for (; e + 2 <= e1; e += 2) {
                const float4* n0 =
                    x4 + (size_t)g_ssrc[e] * C4 + c * 8 + a_q * 2;
                const float4* n1 =
                    x4 + (size_t)g_ssrc[e + 1] * C4 + c * 8 + a_q * 2;
                float4 u0 = n0[0], u1 = n0[1], u2 = n1[0], u3 = n1[1];
                v0.x += u0.x + u2.x; v0.y += u0.y + u2.y;
                v0.z += u0.z + u2.z; v0.w += u0.w + u2.w;
                v1.x += u1.x + u3.x; v1.y += u1.y + u3.y;
                v1.z += u1.z + u3.z; v1.w += u1.w + u3.w;
            }
            if (e < e1) {
                const float4* n0 =
                    x4 + (size_t)g_ssrc[e] * C4 + c * 8 + a_q * 2;
                float4 u0 = n0[0], u1 = n0[1];
                v0.x += u0.x; v0.y += u0.y; v0.z += u0.z; v0.w += u0.w;
                v1.x += u1.x; v1.y += u1.y; v1.z += u1.z; v1.w += u1.w;
            }
        } else {
            v0 = *reinterpret_cast<const float4*>(Ag + c * 32);
            v1 = *reinterpret_cast<const float4*>(Ag + c * 32 + 4);
        }
    };
    auto store_A = [&](int stg, float4 v0, float4 v1) {
        uint32_t h0 = pk(v0.x, v0.y), h1 = pk(v0.z, v0.w);
        uint32_t h2 = pk(v1.x, v1.y), h3 = pk(v1.z, v1.w);
        uint32_t l0 = pk(v0.x - bfr(v0.x), v0.y - bfr(v0.y));
        uint32_t l1 = pk(v0.z - bfr(v0.z), v0.w - bfr(v0.w));
        uint32_t l2 = pk(v1.x - bfr(v1.x), v1.y - bfr(v1.y));
        uint32_t l3 = pk(v1.z - bfr(v1.z), v1.w - bfr(v1.w));
        uint32_t d = a_dst + stg * STAGE_BYTES;
        asm volatile("st.shared.v4.b32 [%0], {%1,%2,%3,%4};" ::"r"(d), "r"(h0),
                     "r"(h1), "r"(h2), "r"(h3));
        asm volatile("st.shared.v4.b32 [%0], {%1,%2,%3,%4};" ::"r"(
                         d + A_LO_OFF),
                     "r"(l0), "r"(l1), "r"(l2), "r"(l3));
    };
    auto compute = [&](int stg) {
        const uint32_t abase = a_lm + stg * STAGE_BYTES;
        const uint32_t bbase = b_lm + stg * STAGE_BYTES;
#pragma unroll
        for (int ks = 0; ks < 2; ks++) {
            uint32_t Ah[2][4], Al[2][4], Bh[8][2], Bl[8][2];
#pragma unroll
            for (int mt = 0; mt < 2; mt++) {
                uint32_t ad = abase + mt * (16 * 80) + ks * 32;
                LDSM4(Ah[mt], ad);
                LDSM4(Al[mt], ad + A_LO_OFF);
            }
#pragma unroll
            for (int nt = 0; nt < 8; nt++) {
                uint32_t bd = bbase + ks * (16 * 528) + nt * 16;
                LDSM2T(Bh[nt], bd);
                LDSM2T(Bl[nt], bd + (B_LO_OFF - B_HI_OFF));
            }
#pragma unroll
            for (int mt = 0; mt < 2; mt++)
#pragma unroll
                for (int nt = 0; nt < 8; nt++) {
                    MMA16816(acc[mt][nt], Ah[mt], Bh[nt]);
                    MMA16816(acc[mt][nt], Al[mt], Bh[nt]);
                    MMA16816(acc[mt][nt], Ah[mt], Bl[nt]);
                }
        }
    };

    // ---- prologue ----
    {
        fill_B(0, 0);
        float4 v0, v1;
        load_A(0, v0, v1);
        store_A(0, v0, v1);
        CP_WAIT0();
        __syncthreads();
    }
    // ---- main loop ----
    for (int c = 0; c < NC; c++) {
        const int s = c & 1;
        const bool nxt = (c + 1 < NC);
        float4 v0, v1;
        if (nxt) {
            fill_B(c + 1, s ^ 1);
            load_A(c + 1, v0, v1);
        }
        compute(s);
        if (nxt) {
            store_A(s ^ 1, v0, v1);
            CP_WAIT0();
            __syncthreads();
        }
    }

    // ---- epilogue: bias + relu, float2 stores ----
#pragma unroll
    for (int mt = 0; mt < 2; mt++) {
        int r0 = bm + warp_m * 32 + mt * 16 + (lane >> 2);
#pragma unroll
        for (int nt = 0; nt < 8; nt++) {
            int col = warp_n * 64 + nt * 8 + (lane & 3) * 2;
            float b0 = bias[col], b1 = bias[col + 1];
            if (r0 < M) {
                float2 o;
                o.x = fmaxf(acc[mt][nt][0] + b0, 0.f);
                o.y = fmaxf(acc[mt][nt][1] + b1, 0.f);
                *reinterpret_cast<float2*>(C + (size_t)r0 * HID + col) = o;
            }
            if (r0 + 8 < M) {
                float2 o;
                o.x = fmaxf(acc[mt][nt][2] + b0, 0.f);
                o.y = fmaxf(acc[mt][nt][3] + b1, 0.f);
                *reinterpret_cast<float2*>(C + (size_t)(r0 + 8) * HID + col) = o;
            }
        }
    }
}

// ---------------------------------------------------------------------------
// Final GEMM: out[M,10] = Z[M,256] @ W[256,10] + b.
// ---------------------------------------------------------------------------
__global__ void gemm_out_k(const float* __restrict__ Z,
                           const float* __restrict__ W,
                           const float* __restrict__ bias,
                           float* __restrict__ out) {
    __shared__ float Ws[NCLS][HID];
    __shared__ float bs[NCLS];
    const int t = threadIdx.x;
    for (int i = t; i < HID * NCLS; i += 256) {
        int k = i / NCLS;
        int c = i - k * NCLS;
        Ws[c][k] = W[i];
    }
    if (t < NCLS) bs[t] = bias[t];
    __syncthreads();

    const int lane = t & 31;
    const int row = blockIdx.x * 8 + (t >> 5);
    if (row >= N_NODES) return;

    const float* zr = Z + (size_t)row * HID;
    float zv[8];
#pragma unroll
    for (int i = 0; i < 8; i++) zv[i] = zr[i * 32 + lane];

#pragma unroll
    for (int c = 0; c < NCLS; c++) {
        float s = 0.f;
#pragma unroll
        for (int i = 0; i < 8; i++) s += zv[i] * Ws[c][i * 32 + lane];
#pragma unroll
        for (int o = 16; o > 0; o >>= 1) s += __shfl_xor_sync(0xffffffffu, s, o);
        if (lane == 0) out[row * NCLS + c] = s + bs[c];
    }
}

// ---------------------------------------------------------------------------
// Launch sequence (default stream; graph-capturable, alloc-free).
// Order chosen so ncu (-s 5 -c 1) lands inside the GEMM block.
// ---------------------------------------------------------------------------
extern "C" void kernel_launch(void* const* d_in, const int* in_sizes, int n_in,
                              void* d_out, int out_size) {
    (void)in_sizes; (void)n_in; (void)out_size;
    const float* x = (const float*)d_in[0];
    const void* ei = d_in[1];
    const float* W1a = (const float*)d_in[2];
    const float* b1a = (const float*)d_in[3];
    const float* W1b = (const float*)d_in[4];
    const float* b1b = (const float*)d_in[5];
    const float* W2a = (const float*)d_in[6];
    const float* b2a = (const float*)d_in[7];
    const float* W2b = (const float*)d_in[8];
    const float* b2b = (const float*)d_in[9];
    float* out = (float*)d_out;

    float *h1, *h, *z;
    __nv_bfloat16 *wp1, *wp2, *wp3;
    cudaGetSymbolAddress((void**)&h1, g_h1);
    cudaGetSymbolAddress((void**)&h, g_h);
    cudaGetSymbolAddress((void**)&z, g_z);
    cudaGetSymbolAddress((void**)&wp1, g_wp1);
    cudaGetSymbolAddress((void**)&wp2, g_wp2);
    cudaGetSymbolAddress((void**)&wp3, g_wp3);

    cudaFuncSetAttribute(gemm_mma<4, true>,
                         cudaFuncAttributeMaxDynamicSharedMemorySize,
                         SMEM_MMA_BYTES);
    cudaFuncSetAttribute(gemm_mma<8, false>,
                         cudaFuncAttributeMaxDynamicSharedMemorySize,
                         SMEM_MMA_BYTES);
    cudaFuncSetAttribute(gemm_mma<8, true>,
                         cudaFuncAttributeMaxDynamicSharedMemorySize,
                         SMEM_MMA_BYTES);

    const int tg = (N_NODES + 127) / 128;  // 782 full-width tiles
    const int scan_blocks = (N_NODES + 1023) / 1024;  // 98

    // ---- setup + CSR build (launches 1..6) ----
    setup_kernel<<<(N_NODES + 255) / 256, 256>>>(W1a, W1b, W2a, wp1, wp2, wp3);
    convert_hist_kernel<<<(N_EDGES + 255) / 256, 256>>>(ei);
    scan1_kernel<<<scan_blocks, 1024>>>();
    scan2_kernel<<<1, 128>>>(scan_blocks);
    scan3_kernel<<<scan_blocks, 1024>>>();
    scatter_kernel<<<(N_EDGES + 255) / 256, 256>>>();

    // ---- layer 1 (7, 8) ----
    gemm_mma<4, true><<<tg, 512, SMEM_MMA_BYTES>>>(x, wp1, b1a, h1, N_NODES);
    gemm_mma<8, false><<<tg, 512, SMEM_MMA_BYTES>>>(h1, wp2, b1b, h, N_NODES);
    // ---- layer 2 (9, 10) ----
    gemm_mma<8, true><<<tg, 512, SMEM_MMA_BYTES>>>(h, wp3, b2a, z, N_NODES);
    gemm_out_k<<<(N_NODES + 7) / 8, 256>>>(z, W2b, b2b, out);
}

// round 14
// speedup vs baseline: 1.0935x; 1.0935x over previous
#include <cuda_runtime.h>
#include <cuda_bf16.h>
#include <cstdint>

#define N_NODES 100000
#define N_EDGES 640000
#define FEAT 128
#define HID 256
#define NCLS 10

// ---------------------------------------------------------------------------
// Persistent scratch (re-initialized every launch before use).
// ---------------------------------------------------------------------------
__device__ __align__(16) float g_agg1[N_NODES * FEAT];
__device__ __align__(16) float g_h1[N_NODES * HID];
__device__ __align__(16) float g_h[N_NODES * HID];
__device__ __align__(16) float g_agg2[N_NODES * HID];
__device__ __align__(16) float g_z[N_NODES * HID];
__device__ int g_src[N_EDGES];
__device__ int g_dst[N_EDGES];
__device__ int g_ssrc[N_EDGES];     // src sorted by dst
__device__ int g_cnt[N_NODES];
__device__ int g_off[N_NODES + 1];
__device__ int g_cur[N_NODES];
__device__ int g_bsum[128];         // scan block sums
// prepped weights, bf16: [chunk][plane(hi,lo)][k(32)][n(256)]
__device__ __align__(16) __nv_bfloat16 g_wp1[4 * 2 * 32 * 256];  // W1a K=128
__device__ __align__(16) __nv_bfloat16 g_wp2[8 * 2 * 32 * 256];  // W1b K=256
__device__ __align__(16) __nv_bfloat16 g_wp3[8 * 2 * 32 * 256];  // W2a K=256

// ---------------------------------------------------------------------------
// mma.sync helpers (legacy tensor-core path; valid at compute_100)
// ---------------------------------------------------------------------------
#define LDSM4(r, a)                                                           \
    asm volatile("ldmatrix.sync.aligned.m8n8.x4.shared.b16 {%0,%1,%2,%3}, [%4];" \
                 : "=r"((r)[0]), "=r"((r)[1]), "=r"((r)[2]), "=r"((r)[3])     \
                 : "r"(a))
#define LDSM2T(r, a)                                                          \
    asm volatile("ldmatrix.sync.aligned.m8n8.x2.trans.shared.b16 {%0,%1}, [%2];" \
                 : "=r"((r)[0]), "=r"((r)[1])                                 \
                 : "r"(a))
#define MMA16816(c, A, B)                                                     \
    asm volatile(                                                             \
        "mma.sync.aligned.m16n8k16.row.col.f32.bf16.bf16.f32 "                \
        "{%0,%1,%2,%3},{%4,%5,%6,%7},{%8,%9},{%0,%1,%2,%3};"                  \
        : "+f"((c)[0]), "+f"((c)[1]), "+f"((c)[2]), "+f"((c)[3])              \
        : "r"((A)[0]), "r"((A)[1]), "r"((A)[2]), "r"((A)[3]), "r"((B)[0]),    \
          "r"((B)[1]))
#define CP_ASYNC16(dst, src)                                                  \
    asm volatile("cp.async.cg.shared.global [%0], [%1], 16;" ::"r"(dst),      \
                 "l"(src) : "memory")
#define CP_COMMIT() asm volatile("cp.async.commit_group;" ::: "memory")
#define CP_WAIT0() asm volatile("cp.async.wait_group 0;" ::: "memory")

__device__ __forceinline__ uint32_t smem_u32(const void* p) {
    uint32_t a;
    asm("{ .reg .u64 t; cvta.to.shared.u64 t, %1; cvt.u32.u64 %0, t; }"
        : "=r"(a) : "l"(p));
    return a;
}
// pack two floats to bf16x2 (lo -> low 16 bits)
__device__ __forceinline__ uint32_t pk(float lo, float hi) {
    uint32_t r;
    asm("cvt.rn.bf16x2.f32 %0, %1, %2;" : "=r"(r) : "f"(hi), "f"(lo));
    return r;
}
__device__ __forceinline__ float bfr(float x) {
    return __bfloat162float(__float2bfloat16(x));
}

// ---------------------------------------------------------------------------
// Fused setup: weight prep (3 matrices) + zero histogram bins.
// Weight layout: [chunk(K/32)][plane(hi,lo)][k(32)][n(256)]
// ---------------------------------------------------------------------------
__device__ __forceinline__ void prep_one(const float* __restrict__ W,
                                         __nv_bfloat16* __restrict__ out,
                                         int i) {
    int k = i >> 8;
    int n = i & 255;
    float v = W[(size_t)k * 256 + n];
    __nv_bfloat16 hi = __float2bfloat16(v);
    __nv_bfloat16 lo = __float2bfloat16(v - __bfloat162float(hi));
    int chunk = k >> 5, kk = k & 31;
    size_t base = ((size_t)chunk * 2 * 32 + kk) * 256 + n;
    out[base] = hi;
    out[base + (size_t)32 * 256] = lo;
}

__global__ void setup_kernel(const float* __restrict__ W1a,
                             const float* __restrict__ W1b,
                             const float* __restrict__ W2a,
                             __nv_bfloat16* __restrict__ wp1,
                             __nv_bfloat16* __restrict__ wp2,
                             __nv_bfloat16* __restrict__ wp3) {
    int i = blockIdx.x * 256 + threadIdx.x;
    if (i < 128 * 256) prep_one(W1a, wp1, i);
    if (i < 256 * 256) {
        prep_one(W1b, wp2, i);
        prep_one(W2a, wp3, i);
    }
    if (i < N_NODES) g_cnt[i] = 0;
}

// ---------------------------------------------------------------------------
// Edge-index conversion + histogram with per-block dtype sniff (JAX may
// demote int64->int32): genuine int64 of values < 2^31 has 0 in every odd
// 32-bit word of the first 256 slots; int32 random data cannot (p~1e-1280).
// ---------------------------------------------------------------------------
__global__ void convert_hist_kernel(const void* __restrict__ ei) {
    __shared__ int s_is64;
    if (threadIdx.x == 0) {
        const unsigned int* w = (const unsigned int*)ei;
        int is64 = 1;
        for (int i = 0; i < 256; i++)
            if (w[2 * i + 1] != 0u) { is64 = 0; break; }
        s_is64 = is64;
    }
    __syncthreads();
    int e = blockIdx.x * 256 + threadIdx.x;
    if (e >= N_EDGES) return;
    int s, d;
    if (s_is64) {
        const long long* p = (const long long*)ei;
        s = (int)p[e];
        d = (int)p[N_EDGES + e];
    } else {
        const int* p = (const int*)ei;
        s = p[e];
        d = p[N_EDGES + e];
    }
    s = min(max(s, 0), N_NODES - 1);
    d = min(max(d, 0), N_NODES - 1);
    g_src[e] = s;
    g_dst[e] = d;
    atomicAdd(&g_cnt[d], 1);
}

// scan step 1: per-block (1024 elems) exclusive scan + block sums
__global__ void scan1_kernel() {
    __shared__ int sh[1024];
    const int tid = threadIdx.x;
    int i = blockIdx.x * 1024 + tid;
    int v = (i < N_NODES) ? g_cnt[i] : 0;
    sh[tid] = v;
    __syncthreads();
#pragma unroll
    for (int o = 1; o < 1024; o <<= 1) {
        int t = (tid >= o) ? sh[tid - o] : 0;
        __syncthreads();
        sh[tid] += t;
        __syncthreads();
    }
    if (i < N_NODES) g_off[i] = sh[tid] - v;
    if (tid == 1023) g_bsum[blockIdx.x] = sh[1023];
}

// scan step 2: exclusive scan over block sums (<=128 entries), one block
__global__ void scan2_kernel(int nb) {
    __shared__ int sh[128];
    const int tid = threadIdx.x;
    int v = (tid < nb) ? g_bsum[tid] : 0;
    sh[tid] = v;
    __syncthreads();
#pragma unroll
    for (int o = 1; o < 128; o <<= 1) {
        int t = (tid >= o) ? sh[tid - o] : 0;
        __syncthreads();
        sh[tid] += t;
        __syncthreads();
    }
    if (tid < nb) g_bsum[tid] = sh[tid] - v;
}

// scan step 3: add block prefix, init cursors, cap sentinel
__global__ void scan3_kernel() {
    int i = blockIdx.x * 1024 + threadIdx.x;
    if (i < N_NODES) {
        int v = g_off[i] + g_bsum[blockIdx.x];
        g_off[i] = v;
        g_cur[i] = v;
    }
    if (i == 0) g_off[N_NODES] = N_EDGES;
}

__global__ void scatter_kernel() {
    int e = blockIdx.x * 256 + threadIdx.x;
    if (e >= N_EDGES) return;
    int d = g_dst[e];
    int pos = atomicAdd(&g_cur[d], 1);
    g_ssrc[pos] = g_src[e];
}

// ---------------------------------------------------------------------------
// CSR aggregation: warp per node. acc = x[node] + sum_{j->node} x[src_j].
// ---------------------------------------------------------------------------
template <int D>
__global__ void agg_csr_kernel(const float* __restrict__ x,
                               float* __restrict__ agg) {
    const int node = blockIdx.x * 8 + (threadIdx.x >> 5);
    if (node >= N_NODES) return;
    const int lane = threadIdx.x & 31;
    constexpr int C = D / 4;
    constexpr int R = C / 32;
    const float4* x4 = reinterpret_cast<const float4*>(x);

    float4 acc[R];
#pragma unroll
    for (int j = 0; j < R; j++)
        acc[j] = x4[(size_t)node * C + j * 32 + lane];

    const int e0 = g_off[node];
    const int e1 = g_off[node + 1];
    for (int e = e0; e < e1; e++) {
        int s = g_ssrc[e];
#pragma unroll
        for (int j = 0; j < R; j++) {
            float4 v = x4[(size_t)s * C + j * 32 + lane];
            acc[j].x += v.x;
            acc[j].y += v.y;
            acc[j].z += v.z;
            acc[j].w += v.w;
        }
    }
    float4* a4 = reinterpret_cast<float4*>(agg);
#pragma unroll
    for (int j = 0; j < R; j++)
        a4[(size_t)node * C + j * 32 + lane] = acc[j];
}

// ---------------------------------------------------------------------------
// bf16x3 mma.sync GEMM, occupancy-tuned: C[M,256] = relu(A[M,K]@W[K,256]+b)
// CTA tile 128m x 64n, 256 threads (8 warps: 4m x 2n), warp tile 32x32,
// BK=32, 2 stages, 2 CTAs/SM. Grid (4 n-tiles, M/128) n-fast so concurrent
// n-tiles share A slabs through L2.
// SMEM/stage: A_hi[128][80B] | A_lo | B_hi[32][144B] | B_lo
// (B stride 144 = 16*9: cp.async-aligned; 36 words % 32 = 4 -> ldmatrix
//  8-row phases cover all banks, conflict-free.)
// ---------------------------------------------------------------------------
#define A_HI_OFF 0
#define A_LO_OFF 10240
#define B_HI_OFF 20480
#define B_LO_OFF 25088                 // B_HI + 32*144
#define STAGE_BYTES 29696              // B_LO + 32*144
#define SMEM_MMA_BYTES (2 * STAGE_BYTES)

template <int NC>  // NC = K/32
__global__ __launch_bounds__(256, 2)
void gemm_mma(const float* __restrict__ A,
              const __nv_bfloat16* __restrict__ wp,
              const float* __restrict__ bias, float* __restrict__ C, int M) {
    extern __shared__ __align__(1024) char smem[];
    const uint32_t sb = smem_u32(smem);
    const int K = NC * 32;
    const int t = threadIdx.x;
    const int lane = t & 31;
    const int warp = t >> 5;
    const int warp_m = warp >> 1;  // 0..3 (32 rows each)
    const int warp_n = warp & 1;   // 0..1 (32 cols each)
    const int bn = blockIdx.x * 64;
    const int bm = blockIdx.y * 128;

    // ---- A fill coords: thread -> (row 0..127, half = 16-float segment) ----
    const int a_row = t >> 1;
    const int a_h = t & 1;
    const bool rok = (bm + a_row) < M;
    const float* Ag = A + (size_t)(bm + a_row) * K + a_h * 16;
    const uint32_t a_dst = sb + a_row * 80 + a_h * 32;

    // ---- ldmatrix per-thread offsets ----
    const int lm_arow = warp_m * 32 + (lane & 7) + ((lane >> 3) & 1) * 8;
    const uint32_t a_lm = sb + lm_arow * 80 + ((lane >> 4) & 1) * 16;
    const uint32_t b_lm = sb + B_HI_OFF + (lane & 15) * 144 + warp_n * 64;

    float acc[2][4][4];
#pragma unroll
    for (int i = 0; i < 2; i++)
#pragma unroll
        for (int j = 0; j < 4; j++)
#pragma unroll
            for (int k = 0; k < 4; k++) acc[i][j][k] = 0.f;

    // ---- helpers ----
    auto fill_B = [&](int c, int stg) {
        // 2 planes x 32 k x 128B = 512 x 16B chunks; 2 per thread
#pragma unroll
        for (int i = 0; i < 2; i++) {
            int f = t + i * 256;
            int pl = f >> 8;
            int k = (f >> 3) & 31;
            int seg = f & 7;
            const __nv_bfloat16* src =
                wp + (((size_t)c * 2 + pl) * 32 + k) * 256 + bn + seg * 8;
            uint32_t dst = sb + stg * STAGE_BYTES +
                           (pl ? B_LO_OFF : B_HI_OFF) + k * 144 + seg * 16;
            CP_ASYNC16(dst, (const void*)src);
        }
        CP_COMMIT();
    };
    auto load_A = [&](int c, float4 v[4]) {
        if (rok) {
#pragma unroll
            for (int j = 0; j < 4; j++)
                v[j] = *reinterpret_cast<const float4*>(Ag + c * 32 + 4 * j);
        } else {
#pragma unroll
            for (int j = 0; j < 4; j++)
                v[j] = make_float4(0.f, 0.f, 0.f, 0.f);
        }
    };
    auto store_A = [&](int stg, const float4 v[4]) {
#pragma unroll
        for (int j = 0; j < 2; j++) {
            const float4 va = v[2 * j], vb = v[2 * j + 1];
            uint32_t d = a_dst + stg * STAGE_BYTES + j * 16;
            asm volatile("st.shared.v4.b32 [%0], {%1,%2,%3,%4};" ::"r"(d),
                         "r"(pk(va.x, va.y)), "r"(pk(va.z, va.w)),
                         "r"(pk(vb.x, vb.y)), "r"(pk(vb.z, vb.w)));
            asm volatile(
                "st.shared.v4.b32 [%0], {%1,%2,%3,%4};" ::"r"(d + A_LO_OFF),
                "r"(pk(va.x - bfr(va.x), va.y - bfr(va.y))),
                "r"(pk(va.z - bfr(va.z), va.w - bfr(va.w))),
                "r"(pk(vb.x - bfr(vb.x), vb.y - bfr(vb.y))),
                "r"(pk(vb.z - bfr(vb.z), vb.w - bfr(vb.w))));
        }
    };
    auto compute = [&](int stg) {
        const uint32_t abase = a_lm + stg * STAGE_BYTES;
        const uint32_t bbase = b_lm + stg * STAGE_BYTES;
#pragma unroll
        for (int ks = 0; ks < 2; ks++) {
            uint32_t Ah[2][4], Al[2][4], Bh[4][2], Bl[4][2];
#pragma unroll
            for (int mt = 0; mt < 2; mt++) {
                uint32_t ad = abase + mt * (16 * 80) + ks * 32;
                LDSM4(Ah[mt], ad);
                LDSM4(Al[mt], ad + A_LO_OFF);
            }
#pragma unroll
            for (int nt = 0; nt < 4; nt++) {
                uint32_t bd = bbase + ks * (16 * 144) + nt * 16;
                LDSM2T(Bh[nt], bd);
                LDSM2T(Bl[nt], bd + (B_LO_OFF - B_HI_OFF));
            }
#pragma unroll
            for (int mt = 0; mt < 2; mt++)
#pragma unroll
                for (int nt = 0; nt < 4; nt++) {
                    MMA16816(acc[mt][nt], Ah[mt], Bh[nt]);
                    MMA16816(acc[mt][nt], Al[mt], Bh[nt]);
                    MMA16816(acc[mt][nt], Ah[mt], Bl[nt]);
                }
        }
    };

    // ---- prologue ----
    {
        fill_B(0, 0);
        float4 v[4];
        load_A(0, v);
        store_A(0, v);
        CP_WAIT0();
        __syncthreads();
    }
    // ---- main loop ----
    for (int c = 0; c < NC; c++) {
        const int s = c & 1;
        const bool nxt = (c + 1 < NC);
        float4 v[4];
        if (nxt) {
            fill_B(c + 1, s ^ 1);
            load_A(c + 1, v);
        }
        compute(s);
        if (nxt) {
            store_A(s ^ 1, v);
            CP_WAIT0();
            __syncthreads();
        }
    }

    // ---- epilogue: bias + relu, float2 stores ----
#pragma unroll
    for (int mt = 0; mt < 2; mt++) {
        int r0 = bm + warp_m * 32 + mt * 16 + (lane >> 2);
#pragma unroll
        for (int nt = 0; nt < 4; nt++) {
            int col = bn + warp_n * 32 + nt * 8 + (lane & 3) * 2;
            float b0 = bias[col], b1 = bias[col + 1];
            if (r0 < M) {
                float2 o;
                o.x = fmaxf(acc[mt][nt][0] + b0, 0.f);
                o.y = fmaxf(acc[mt][nt][1] + b1, 0.f);
                *reinterpret_cast<float2*>(C + (size_t)r0 * HID + col) = o;
            }
            if (r0 + 8 < M) {
                float2 o;
                o.x = fmaxf(acc[mt][nt][2] + b0, 0.f);
                o.y = fmaxf(acc[mt][nt][3] + b1, 0.f);
                *reinterpret_cast<float2*>(C + (size_t)(r0 + 8) * HID + col) = o;
            }
        }
    }
}

// ---------------------------------------------------------------------------
// Final GEMM: out[M,10] = Z[M,256] @ W[256,10] + b.
// ---------------------------------------------------------------------------
__global__ void gemm_out_k(const float* __restrict__ Z,
                           const float* __restrict__ W,
                           const float* __restrict__ bias,
                           float* __restrict__ out) {
    __shared__ float Ws[NCLS][HID];
    __shared__ float bs[NCLS];
    const int t = threadIdx.x;
    for (int i = t; i < HID * NCLS; i += 256) {
        int k = i / NCLS;
        int c = i - k * NCLS;
        Ws[c][k] = W[i];
    }
    if (t < NCLS) bs[t] = bias[t];
    __syncthreads();

    const int lane = t & 31;
    const int row = blockIdx.x * 8 + (t >> 5);
    if (row >= N_NODES) return;

    const float* zr = Z + (size_t)row * HID;
    float zv[8];
#pragma unroll
    for (int i = 0; i < 8; i++) zv[i] = zr[i * 32 + lane];

#pragma unroll
    for (int c = 0; c < NCLS; c++) {
        float s = 0.f;
#pragma unroll
        for (int i = 0; i < 8; i++) s += zv[i] * Ws[c][i * 32 + lane];
#pragma unroll
        for (int o = 16; o > 0; o >>= 1) s += __shfl_xor_sync(0xffffffffu, s, o);
        if (lane == 0) out[row * NCLS + c] = s + bs[c];
    }
}

// ---------------------------------------------------------------------------
// Launch sequence (default stream; graph-capturable, alloc-free)
// ---------------------------------------------------------------------------
extern "C" void kernel_launch(void* const* d_in, const int* in_sizes, int n_in,
                              void* d_out, int out_size) {
    (void)in_sizes; (void)n_in; (void)out_size;
    const float* x = (const float*)d_in[0];
    const void* ei = d_in[1];
    const float* W1a = (const float*)d_in[2];
    const float* b1a = (const float*)d_in[3];
    const float* W1b = (const float*)d_in[4];
    const float* b1b = (const float*)d_in[5];
    const float* W2a = (const float*)d_in[6];
    const float* b2a = (const float*)d_in[7];
    const float* W2b = (const float*)d_in[8];
    const float* b2b = (const float*)d_in[9];
    float* out = (float*)d_out;

    float *agg1, *h1, *h, *agg2, *z;
    __nv_bfloat16 *wp1, *wp2, *wp3;
    cudaGetSymbolAddress((void**)&agg1, g_agg1);
    cudaGetSymbolAddress((void**)&h1, g_h1);
    cudaGetSymbolAddress((void**)&h, g_h);
    cudaGetSymbolAddress((void**)&agg2, g_agg2);
    cudaGetSymbolAddress((void**)&z, g_z);
    cudaGetSymbolAddress((void**)&wp1, g_wp1);
    cudaGetSymbolAddress((void**)&wp2, g_wp2);
    cudaGetSymbolAddress((void**)&wp3, g_wp3);

    cudaFuncSetAttribute(gemm_mma<4>,
                         cudaFuncAttributeMaxDynamicSharedMemorySize,
                         SMEM_MMA_BYTES);
    cudaFuncSetAttribute(gemm_mma<8>,
                         cudaFuncAttributeMaxDynamicSharedMemorySize,
                         SMEM_MMA_BYTES);

    // ---- setup + CSR build ----
    const int scan_blocks = (N_NODES + 1023) / 1024;  // 98
    setup_kernel<<<(N_NODES + 255) / 256, 256>>>(W1a, W1b, W2a, wp1, wp2, wp3);
    convert_hist_kernel<<<(N_EDGES + 255) / 256, 256>>>(ei);
    scan1_kernel<<<scan_blocks, 1024>>>();
    scan2_kernel<<<1, 128>>>(scan_blocks);
    scan3_kernel<<<scan_blocks, 1024>>>();
    scatter_kernel<<<(N_EDGES + 255) / 256, 256>>>();

    const dim3 tg(4, (N_NODES + 127) / 128);  // n-fast: A slabs shared in L2
    const int agg_blocks = (N_NODES + 7) / 8;

    // ---- layer 1 ----
    agg_csr_kernel<FEAT><<<agg_blocks, 256>>>(x, agg1);
    gemm_mma<4><<<tg, 256, SMEM_MMA_BYTES>>>(agg1, wp1, b1a, h1, N_NODES);
    gemm_mma<8><<<tg, 256, SMEM_MMA_BYTES>>>(h1, wp2, b1b, h, N_NODES);
    // ---- layer 2 ----
    agg_csr_kernel<HID><<<agg_blocks, 256>>>(h, agg2);
    gemm_mma<8><<<tg, 256, SMEM_MMA_BYTES>>>(agg2, wp3, b2a, z, N_NODES);
    gemm_out_k<<<(N_NODES + 7) / 8, 256>>>(z, W2b, b2b, out);
}

// round 15
// speedup vs baseline: 1.5778x; 1.4429x over previous
#include <cuda_runtime.h>
#include <cuda_fp16.h>
#include <cstdint>

#define N_NODES 100000
#define N_EDGES 640000
#define FEAT 128
#define HID 256
#define NCLS 10

// ---------------------------------------------------------------------------
// Persistent scratch (re-initialized every launch before use).
// ---------------------------------------------------------------------------
__device__ __align__(16) float g_agg1[N_NODES * FEAT];
__device__ __align__(16) float g_h1[N_NODES * HID];
__device__ __align__(16) float g_h[N_NODES * HID];
__device__ __align__(16) float g_agg2[N_NODES * HID];
__device__ __align__(16) float g_z[N_NODES * HID];
__device__ int g_src[N_EDGES];
__device__ int g_dst[N_EDGES];
__device__ int g_ssrc[N_EDGES];     // src sorted by dst
__device__ int g_cnt[N_NODES];
__device__ int g_off[N_NODES + 1];
__device__ int g_cur[N_NODES];
__device__ int g_bsum[128];         // scan block sums
// prepped weights, fp16 row-major [k][n(256)]
__device__ __align__(16) __half g_wp1[128 * 256];  // W1a
__device__ __align__(16) __half g_wp2[256 * 256];  // W1b
__device__ __align__(16) __half g_wp3[256 * 256];  // W2a

// ---------------------------------------------------------------------------
// mma.sync helpers (legacy tensor-core path; valid at compute_100)
// ---------------------------------------------------------------------------
#define LDSM4(r, a)                                                           \
    asm volatile("ldmatrix.sync.aligned.m8n8.x4.shared.b16 {%0,%1,%2,%3}, [%4];" \
                 : "=r"((r)[0]), "=r"((r)[1]), "=r"((r)[2]), "=r"((r)[3])     \
                 : "r"(a))
#define LDSM2T(r, a)                                                          \
    asm volatile("ldmatrix.sync.aligned.m8n8.x2.trans.shared.b16 {%0,%1}, [%2];" \
                 : "=r"((r)[0]), "=r"((r)[1])                                 \
                 : "r"(a))
#define MMA16816F(c, A, B)                                                    \
    asm volatile(                                                             \
        "mma.sync.aligned.m16n8k16.row.col.f32.f16.f16.f32 "                  \
        "{%0,%1,%2,%3},{%4,%5,%6,%7},{%8,%9},{%0,%1,%2,%3};"                  \
        : "+f"((c)[0]), "+f"((c)[1]), "+f"((c)[2]), "+f"((c)[3])              \
        : "r"((A)[0]), "r"((A)[1]), "r"((A)[2]), "r"((A)[3]), "r"((B)[0]),    \
          "r"((B)[1]))
#define CP_ASYNC16(dst, src)                                                  \
    asm volatile("cp.async.cg.shared.global [%0], [%1], 16;" ::"r"(dst),      \
                 "l"(src) : "memory")
#define CP_COMMIT() asm volatile("cp.async.commit_group;" ::: "memory")
#define CP_WAIT0() asm volatile("cp.async.wait_group 0;" ::: "memory")

__device__ __forceinline__ uint32_t smem_u32(const void* p) {
    uint32_t a;
    asm("{ .reg .u64 t; cvta.to.shared.u64 t, %1; cvt.u32.u64 %0, t; }"
        : "=r"(a) : "l"(p));
    return a;
}
// pack two floats to f16x2 (first arg -> low 16 bits = earlier k)
__device__ __forceinline__ uint32_t pkh(float lo, float hi) {
    __half2 h = __floats2half2_rn(lo, hi);
    return *reinterpret_cast<uint32_t*>(&h);
}

// ---------------------------------------------------------------------------
// Fused setup: weight prep (fp32 -> fp16, row-major) + zero histogram bins.
// ---------------------------------------------------------------------------
__global__ void setup_kernel(const float* __restrict__ W1a,
                             const float* __restrict__ W1b,
                             const float* __restrict__ W2a) {
    int i = blockIdx.x * 256 + threadIdx.x;
    if (i < 128 * 256) g_wp1[i] = __float2half(W1a[i]);
    if (i < 256 * 256) {
        g_wp2[i] = __float2half(W1b[i]);
        g_wp3[i] = __float2half(W2a[i]);
    }
    if (i < N_NODES) g_cnt[i] = 0;
}

// ---------------------------------------------------------------------------
// Edge-index conversion + histogram with per-block dtype sniff (JAX may
// demote int64->int32): genuine int64 of values < 2^31 has 0 in every odd
// 32-bit word of the first 256 slots; int32 random data cannot (p~1e-1280).
// ---------------------------------------------------------------------------
__global__ void convert_hist_kernel(const void* __restrict__ ei) {
    __shared__ int s_is64;
    if (threadIdx.x == 0) {
        const unsigned int* w = (const unsigned int*)ei;
        int is64 = 1;
        for (int i = 0; i < 256; i++)
            if (w[2 * i + 1] != 0u) { is64 = 0; break; }
        s_is64 = is64;
    }
    __syncthreads();
    int e = blockIdx.x * 256 + threadIdx.x;
    if (e >= N_EDGES) return;
    int s, d;
    if (s_is64) {
        const long long* p = (const long long*)ei;
        s = (int)p[e];
        d = (int)p[N_EDGES + e];
    } else {
        const int* p = (const int*)ei;
        s = p[e];
        d = p[N_EDGES + e];
    }
    s = min(max(s, 0), N_NODES - 1);
    d = min(max(d, 0), N_NODES - 1);
    g_src[e] = s;
    g_dst[e] = d;
    atomicAdd(&g_cnt[d], 1);
}

// scan step 1: per-block (1024 elems) exclusive scan + block sums
__global__ void scan1_kernel() {
    __shared__ int sh[1024];
    const int tid = threadIdx.x;
    int i = blockIdx.x * 1024 + tid;
    int v = (i < N_NODES) ? g_cnt[i] : 0;
    sh[tid] = v;
    __syncthreads();
#pragma unroll
    for (int o = 1; o < 1024; o <<= 1) {
        int t = (tid >= o) ? sh[tid - o] : 0;
        __syncthreads();
        sh[tid] += t;
        __syncthreads();
    }
    if (i < N_NODES) g_off[i] = sh[tid] - v;
    if (tid == 1023) g_bsum[blockIdx.x] = sh[1023];
}

// scan step 2: exclusive scan over block sums (<=128 entries), one block
__global__ void scan2_kernel(int nb) {
    __shared__ int sh[128];
    const int tid = threadIdx.x;
    int v = (tid < nb) ? g_bsum[tid] : 0;
    sh[tid] = v;
    __syncthreads();
#pragma unroll
    for (int o = 1; o < 128; o <<= 1) {
        int t = (tid >= o) ? sh[tid - o] : 0;
        __syncthreads();
        sh[tid] += t;
        __syncthreads();
    }
    if (tid < nb) g_bsum[tid] = sh[tid] - v;
}

// scan step 3: add block prefix, init cursors, cap sentinel
__global__ void scan3_kernel() {
    int i = blockIdx.x * 1024 + threadIdx.x;
    if (i < N_NODES) {
        int v = g_off[i] + g_bsum[blockIdx.x];
        g_off[i] = v;
        g_cur[i] = v;
    }
    if (i == 0) g_off[N_NODES] = N_EDGES;
}

__global__ void scatter_kernel() {
    int e = blockIdx.x * 256 + threadIdx.x;
    if (e >= N_EDGES) return;
    int d = g_dst[e];
    int pos = atomicAdd(&g_cur[d], 1);
    g_ssrc[pos] = g_src[e];
}

// ---------------------------------------------------------------------------
// CSR aggregation: warp per node. acc = x[node] + sum_{j->node} x[src_j].
// ---------------------------------------------------------------------------
template <int D>
__global__ void agg_csr_kernel(const float* __restrict__ x,
                               float* __restrict__ agg) {
    const int node = blockIdx.x * 8 + (threadIdx.x >> 5);
    if (node >= N_NODES) return;
    const int lane = threadIdx.x & 31;
    constexpr int C = D / 4;
    constexpr int R = C / 32;
    const float4* x4 = reinterpret_cast<const float4*>(x);

    float4 acc[R];
#pragma unroll
    for (int j = 0; j < R; j++)
        acc[j] = x4[(size_t)node * C + j * 32 + lane];

    const int e0 = g_off[node];
    const int e1 = g_off[node + 1];
    for (int e = e0; e < e1; e++) {
        int s = g_ssrc[e];
#pragma unroll
        for (int j = 0; j < R; j++) {
            float4 v = x4[(size_t)s * C + j * 32 + lane];
            acc[j].x += v.x;
            acc[j].y += v.y;
            acc[j].z += v.z;
            acc[j].w += v.w;
        }
    }
    float4* a4 = reinterpret_cast<float4*>(agg);
#pragma unroll
    for (int j = 0; j < R; j++)
        a4[(size_t)node * C + j * 32 + lane] = acc[j];
}

// ---------------------------------------------------------------------------
// fp16 single-plane mma.sync GEMM, full-width tile:
// C[M,256] = relu(A[M,K] @ W[K,256] + bias)
// CTA 128x256, 512 threads (16 warps 4m x 4n), warp tile 32x64, BK=32,
// 2 stages. SMEM/stage: A[128 rows][80B] | B[32 k-rows][528B]
// (strides 80 = 16*5 and 528 = 16*33: cp.async-aligned, ldmatrix
//  conflict-free; both proven in the bf16 variants.)
// ---------------------------------------------------------------------------
#define A_OFF 0
#define B_OFF 10240                    // 128*80
#define STAGE_BYTES 27136              // B_OFF + 32*528
#define SMEM_MMA_BYTES (2 * STAGE_BYTES)

template <int NC>  // NC = K/32
__global__ __launch_bounds__(512)
void gemm_mma(const float* __restrict__ A, const __half* __restrict__ wp,
              const float* __restrict__ bias, float* __restrict__ C, int M) {
    extern __shared__ __align__(1024) char smem[];
    const uint32_t sb = smem_u32(smem);
    const int K = NC * 32;
    const int t = threadIdx.x;
    const int lane = t & 31;
    const int warp = t >> 5;
    const int warp_m = warp >> 2;  // 0..3 (32 rows each)
    const int warp_n = warp & 3;   // 0..3 (64 cols each)
    const int bm = blockIdx.x * 128;

    // ---- A fill coords: thread -> (row 0..127, q = 8-float segment) ----
    const int a_row = t >> 2;
    const int a_q = t & 3;
    const bool rok = (bm + a_row) < M;
    const float* Ag = A + (size_t)(bm + a_row) * K + a_q * 8;
    const uint32_t a_dst = sb + a_row * 80 + a_q * 16;

    // ---- ldmatrix per-thread offsets ----
    const int lm_arow = warp_m * 32 + (lane & 7) + ((lane >> 3) & 1) * 8;
    const uint32_t a_lm = sb + lm_arow * 80 + ((lane >> 4) & 1) * 16;
    const uint32_t b_lm = sb + B_OFF + (lane & 15) * 528 + warp_n * 128;

    float acc[2][8][4];
#pragma unroll
    for (int i = 0; i < 2; i++)
#pragma unroll
        for (int j = 0; j < 8; j++)
#pragma unroll
            for (int k = 0; k < 4; k++) acc[i][j][k] = 0.f;

    // ---- helpers ----
    auto fill_B = [&](int c, int stg) {
        // 32 k-rows x 512B = 1024 x 16B chunks; 2 per thread
#pragma unroll
        for (int i = 0; i < 2; i++) {
            int f = t + i * 512;
            int k = (f >> 5) & 31;
            int seg = f & 31;
            const __half* src = wp + ((size_t)c * 32 + k) * 256 + seg * 8;
            uint32_t dst =
                sb + stg * STAGE_BYTES + B_OFF + k * 528 + seg * 16;
            CP_ASYNC16(dst, (const void*)src);
        }
        CP_COMMIT();
    };
    auto load_A = [&](int c, float4& v0, float4& v1) {
        if (rok) {
            v0 = *reinterpret_cast<const float4*>(Ag + c * 32);
            v1 = *reinterpret_cast<const float4*>(Ag + c * 32 + 4);
        } else {
            v0 = make_float4(0.f, 0.f, 0.f, 0.f);
            v1 = v0;
        }
    };
    auto store_A = [&](int stg, float4 v0, float4 v1) {
        uint32_t h0 = pkh(v0.x, v0.y), h1 = pkh(v0.z, v0.w);
        uint32_t h2 = pkh(v1.x, v1.y), h3 = pkh(v1.z, v1.w);
        uint32_t d = a_dst + stg * STAGE_BYTES;
        asm volatile("st.shared.v4.b32 [%0], {%1,%2,%3,%4};" ::"r"(d), "r"(h0),
                     "r"(h1), "r"(h2), "r"(h3));
    };
    auto compute = [&](int stg) {
        const uint32_t abase = a_lm + stg * STAGE_BYTES;
        const uint32_t bbase = b_lm + stg * STAGE_BYTES;
#pragma unroll
        for (int ks = 0; ks < 2; ks++) {
            uint32_t Ah[2][4], Bh[8][2];
#pragma unroll
            for (int mt = 0; mt < 2; mt++)
                LDSM4(Ah[mt], abase + mt * (16 * 80) + ks * 32);
#pragma unroll
            for (int nt = 0; nt < 8; nt++)
                LDSM2T(Bh[nt], bbase + ks * (16 * 528) + nt * 16);
#pragma unroll
            for (int mt = 0; mt < 2; mt++)
#pragma unroll
                for (int nt = 0; nt < 8; nt++)
                    MMA16816F(acc[mt][nt], Ah[mt], Bh[nt]);
        }
    };

    // ---- prologue ----
    {
        fill_B(0, 0);
        float4 v0, v1;
        load_A(0, v0, v1);
        store_A(0, v0, v1);
        CP_WAIT0();
        __syncthreads();
    }
    // ---- main loop ----
    for (int c = 0; c < NC; c++) {
        const int s = c & 1;
        const bool nxt = (c + 1 < NC);
        float4 v0, v1;
        if (nxt) {
            fill_B(c + 1, s ^ 1);
            load_A(c + 1, v0, v1);
        }
        compute(s);
        if (nxt) {
            store_A(s ^ 1, v0, v1);
            CP_WAIT0();
            __syncthreads();
        }
    }

    // ---- epilogue: bias + relu, float2 stores ----
#pragma unroll
    for (int mt = 0; mt < 2; mt++) {
        int r0 = bm + warp_m * 32 + mt * 16 + (lane >> 2);
#pragma unroll
        for (int nt = 0; nt < 8; nt++) {
            int col = warp_n * 64 + nt * 8 + (lane & 3) * 2;
            float b0 = bias[col], b1 = bias[col + 1];
            if (r0 < M) {
                float2 o;
                o.x = fmaxf(acc[mt][nt][0] + b0, 0.f);
                o.y = fmaxf(acc[mt][nt][1] + b1, 0.f);
                *reinterpret_cast<float2*>(C + (size_t)r0 * HID + col) = o;
            }
            if (r0 + 8 < M) {
                float2 o;
                o.x = fmaxf(acc[mt][nt][2] + b0, 0.f);
                o.y = fmaxf(acc[mt][nt][3] + b1, 0.f);
                *reinterpret_cast<float2*>(C + (size_t)(r0 + 8) * HID + col) = o;
            }
        }
    }
}

// ---------------------------------------------------------------------------
// Final GEMM: out[M,10] = Z[M,256] @ W[256,10] + b. (fp32)
// ---------------------------------------------------------------------------
__global__ void gemm_out_k(const float* __restrict__ Z,
                           const float* __restrict__ W,
                           const float* __restrict__ bias,
                           float* __restrict__ out) {
    __shared__ float Ws[NCLS][HID];
    __shared__ float bs[NCLS];
    const int t = threadIdx.x;
    for (int i = t; i < HID * NCLS; i += 256) {
        int k = i / NCLS;
        int c = i - k * NCLS;
        Ws[c][k] = W[i];
    }
    if (t < NCLS) bs[t] = bias[t];
    __syncthreads();

    const int lane = t & 31;
    const int row = blockIdx.x * 8 + (t >> 5);
    if (row >= N_NODES) return;

    const float* zr = Z + (size_t)row * HID;
    float zv[8];
#pragma unroll
    for (int i = 0; i < 8; i++) zv[i] = zr[i * 32 + lane];

#pragma unroll
    for (int c = 0; c < NCLS; c++) {
        float s = 0.f;
#pragma unroll
        for (int i = 0; i < 8; i++) s += zv[i] * Ws[c][i * 32 + lane];
#pragma unroll
        for (int o = 16; o > 0; o >>= 1) s += __shfl_xor_sync(0xffffffffu, s, o);
        if (lane == 0) out[row * NCLS + c] = s + bs[c];
    }
}

// ---------------------------------------------------------------------------
// Launch sequence (default stream; graph-capturable, alloc-free)
// ---------------------------------------------------------------------------
extern "C" void kernel_launch(void* const* d_in, const int* in_sizes, int n_in,
                              void* d_out, int out_size) {
    (void)in_sizes; (void)n_in; (void)out_size;
    const float* x = (const float*)d_in[0];
    const void* ei = d_in[1];
    const float* W1a = (const float*)d_in[2];
    const float* b1a = (const float*)d_in[3];
    const float* W1b = (const float*)d_in[4];
    const float* b1b = (const float*)d_in[5];
    const float* W2a = (const float*)d_in[6];
    const float* b2a = (const float*)d_in[7];
    const float* W2b = (const float*)d_in[8];
    const float* b2b = (const float*)d_in[9];
    float* out = (float*)d_out;

    float *agg1, *h1, *h, *agg2, *z;
    __half *wp1, *wp2, *wp3;
    cudaGetSymbolAddress((void**)&agg1, g_agg1);
    cudaGetSymbolAddress((void**)&h1, g_h1);
    cudaGetSymbolAddress((void**)&h, g_h);
    cudaGetSymbolAddress((void**)&agg2, g_agg2);
    cudaGetSymbolAddress((void**)&z, g_z);
    cudaGetSymbolAddress((void**)&wp1, g_wp1);
    cudaGetSymbolAddress((void**)&wp2, g_wp2);
    cudaGetSymbolAddress((void**)&wp3, g_wp3);

    cudaFuncSetAttribute(gemm_mma<4>,
                         cudaFuncAttributeMaxDynamicSharedMemorySize,
                         SMEM_MMA_BYTES);
    cudaFuncSetAttribute(gemm_mma<8>,
                         cudaFuncAttributeMaxDynamicSharedMemorySize,
                         SMEM_MMA_BYTES);

    // ---- setup + CSR build ----
    const int scan_blocks = (N_NODES + 1023) / 1024;  // 98
    setup_kernel<<<(N_NODES + 255) / 256, 256>>>(W1a, W1b, W2a);
    convert_hist_kernel<<<(N_EDGES + 255) / 256, 256>>>(ei);
    scan1_kernel<<<scan_blocks, 1024>>>();
    scan2_kernel<<<1, 128>>>(scan_blocks);
    scan3_kernel<<<scan_blocks, 1024>>>();
    scatter_kernel<<<(N_EDGES + 255) / 256, 256>>>();

    const int tg = (N_NODES + 127) / 128;  // 782 full-width tiles
    const int agg_blocks = (N_NODES + 7) / 8;

    // ---- layer 1 ----
    agg_csr_kernel<FEAT><<<agg_blocks, 256>>>(x, agg1);
    gemm_mma<4><<<tg, 512, SMEM_MMA_BYTES>>>(agg1, wp1, b1a, h1, N_NODES);
    gemm_mma<8><<<tg, 512, SMEM_MMA_BYTES>>>(h1, wp2, b1b, h, N_NODES);
    // ---- layer 2 ----
    agg_csr_kernel<HID><<<agg_blocks, 256>>>(h, agg2);
    gemm_mma<8><<<tg, 512, SMEM_MMA_BYTES>>>(agg2, wp3, b2a, z, N_NODES);
    gemm_out_k<<<(N_NODES + 7) / 8, 256>>>(z, W2b, b2b, out);
}

// round 16
// speedup vs baseline: 1.8852x; 1.1948x over previous
#include <cuda_runtime.h>
#include <cuda_fp16.h>
#include <cstdint>

#define N_NODES 100000
#define N_EDGES 640000
#define FEAT 128
#define HID 256
#define NCLS 10

// ---------------------------------------------------------------------------
// Persistent scratch (re-initialized every launch before use).
// Activations stored fp16 (z kept fp32 for final-GEMM accuracy).
// ---------------------------------------------------------------------------
__device__ __align__(16) __half g_agg1[N_NODES * FEAT];
__device__ __align__(16) __half g_h1[N_NODES * HID];
__device__ __align__(16) __half g_h[N_NODES * HID];
__device__ __align__(16) __half g_agg2[N_NODES * HID];
__device__ __align__(16) float g_z[N_NODES * HID];
__device__ int g_src[N_EDGES];
__device__ int g_dst[N_EDGES];
__device__ int g_ssrc[N_EDGES];     // src sorted by dst
__device__ int g_cnt[N_NODES];
__device__ int g_off[N_NODES + 1];
__device__ int g_cur[N_NODES];
__device__ int g_bsum[128];         // scan block sums
// prepped weights, fp16 row-major [k][n(256)]
__device__ __align__(16) __half g_wp1[128 * 256];  // W1a
__device__ __align__(16) __half g_wp2[256 * 256];  // W1b
__device__ __align__(16) __half g_wp3[256 * 256];  // W2a

// ---------------------------------------------------------------------------
// mma.sync helpers (legacy tensor-core path; valid at compute_100)
// ---------------------------------------------------------------------------
#define LDSM4(r, a)                                                           \
    asm volatile("ldmatrix.sync.aligned.m8n8.x4.shared.b16 {%0,%1,%2,%3}, [%4];" \
                 : "=r"((r)[0]), "=r"((r)[1]), "=r"((r)[2]), "=r"((r)[3])     \
                 : "r"(a))
#define LDSM2T(r, a)                                                          \
    asm volatile("ldmatrix.sync.aligned.m8n8.x2.trans.shared.b16 {%0,%1}, [%2];" \
                 : "=r"((r)[0]), "=r"((r)[1])                                 \
                 : "r"(a))
#define MMA16816F(c, A, B)                                                    \
    asm volatile(                                                             \
        "mma.sync.aligned.m16n8k16.row.col.f32.f16.f16.f32 "                  \
        "{%0,%1,%2,%3},{%4,%5,%6,%7},{%8,%9},{%0,%1,%2,%3};"                  \
        : "+f"((c)[0]), "+f"((c)[1]), "+f"((c)[2]), "+f"((c)[3])              \
        : "r"((A)[0]), "r"((A)[1]), "r"((A)[2]), "r"((A)[3]), "r"((B)[0]),    \
          "r"((B)[1]))
#define CP_ASYNC16(dst, src)                                                  \
    asm volatile("cp.async.cg.shared.global [%0], [%1], 16;" ::"r"(dst),      \
                 "l"(src) : "memory")
#define CP_COMMIT() asm volatile("cp.async.commit_group;" ::: "memory")
#define CP_WAIT0() asm volatile("cp.async.wait_group 0;" ::: "memory")

__device__ __forceinline__ uint32_t smem_u32(const void* p) {
    uint32_t a;
    asm("{ .reg .u64 t; cvta.to.shared.u64 t, %1; cvt.u32.u64 %0, t; }"
        : "=r"(a) : "l"(p));
    return a;
}
__device__ __forceinline__ uint32_t pkh(float lo, float hi) {
    __half2 h = __floats2half2_rn(lo, hi);
    return *reinterpret_cast<uint32_t*>(&h);
}
__device__ __forceinline__ float2 h2f(uint32_t u) {
    __half2 h = *reinterpret_cast<__half2*>(&u);
    return __half22float2(h);
}

// ---------------------------------------------------------------------------
// Fused setup: weight prep (fp32 -> fp16 row-major) + zero histogram bins.
// ---------------------------------------------------------------------------
__global__ void setup_kernel(const float* __restrict__ W1a,
                             const float* __restrict__ W1b,
                             const float* __restrict__ W2a) {
    int i = blockIdx.x * 256 + threadIdx.x;
    if (i < 128 * 256) g_wp1[i] = __float2half(W1a[i]);
    if (i < 256 * 256) {
        g_wp2[i] = __float2half(W1b[i]);
        g_wp3[i] = __float2half(W2a[i]);
    }
    if (i < N_NODES) g_cnt[i] = 0;
}

// ---------------------------------------------------------------------------
// Edge-index conversion + histogram with per-block dtype sniff (JAX may
// demote int64->int32): genuine int64 of values < 2^31 has 0 in every odd
// 32-bit word of the first 256 slots; int32 random data cannot (p~1e-1280).
// ---------------------------------------------------------------------------
__global__ void convert_hist_kernel(const void* __restrict__ ei) {
    __shared__ int s_is64;
    if (threadIdx.x == 0) {
        const unsigned int* w = (const unsigned int*)ei;
        int is64 = 1;
        for (int i = 0; i < 256; i++)
            if (w[2 * i + 1] != 0u) { is64 = 0; break; }
        s_is64 = is64;
    }
    __syncthreads();
    int e = blockIdx.x * 256 + threadIdx.x;
    if (e >= N_EDGES) return;
    int s, d;
    if (s_is64) {
        const long long* p = (const long long*)ei;
        s = (int)p[e];
        d = (int)p[N_EDGES + e];
    } else {
        const int* p = (const int*)ei;
        s = p[e];
        d = p[N_EDGES + e];
    }
    s = min(max(s, 0), N_NODES - 1);
    d = min(max(d, 0), N_NODES - 1);
    g_src[e] = s;
    g_dst[e] = d;
    atomicAdd(&g_cnt[d], 1);
}

// scan step 1: per-block (1024 elems) exclusive scan + block sums
__global__ void scan1_kernel() {
    __shared__ int sh[1024];
    const int tid = threadIdx.x;
    int i = blockIdx.x * 1024 + tid;
    int v = (i < N_NODES) ? g_cnt[i] : 0;
    sh[tid] = v;
    __syncthreads();
#pragma unroll
    for (int o = 1; o < 1024; o <<= 1) {
        int t = (tid >= o) ? sh[tid - o] : 0;
        __syncthreads();
        sh[tid] += t;
        __syncthreads();
    }
    if (i < N_NODES) g_off[i] = sh[tid] - v;
    if (tid == 1023) g_bsum[blockIdx.x] = sh[1023];
}

// scan step 2: exclusive scan over block sums (<=128 entries), one block
__global__ void scan2_kernel(int nb) {
    __shared__ int sh[128];
    const int tid = threadIdx.x;
    int v = (tid < nb) ? g_bsum[tid] : 0;
    sh[tid] = v;
    __syncthreads();
#pragma unroll
    for (int o = 1; o < 128; o <<= 1) {
        int t = (tid >= o) ? sh[tid - o] : 0;
        __syncthreads();
        sh[tid] += t;
        __syncthreads();
    }
    if (tid < nb) g_bsum[tid] = sh[tid] - v;
}

// scan step 3: add block prefix, init cursors, cap sentinel
__global__ void scan3_kernel() {
    int i = blockIdx.x * 1024 + threadIdx.x;
    if (i < N_NODES) {
        int v = g_off[i] + g_bsum[blockIdx.x];
        g_off[i] = v;
        g_cur[i] = v;
    }
    if (i == 0) g_off[N_NODES] = N_EDGES;
}

__global__ void scatter_kernel() {
    int e = blockIdx.x * 256 + threadIdx.x;
    if (e >= N_EDGES) return;
    int d = g_dst[e];
    int pos = atomicAdd(&g_cur[d], 1);
    g_ssrc[pos] = g_src[e];
}

// ---------------------------------------------------------------------------
// Aggregation layer 1: fp32 x in, fp16 agg out. Warp per node; lane holds
// one float4 (FEAT=128 -> 32 float4/row).
// ---------------------------------------------------------------------------
__global__ void agg1_kernel(const float* __restrict__ x,
                            __half* __restrict__ agg) {
    const int node = blockIdx.x * 8 + (threadIdx.x >> 5);
    if (node >= N_NODES) return;
    const int lane = threadIdx.x & 31;
    const float4* x4 = reinterpret_cast<const float4*>(x);

    float4 acc = x4[(size_t)node * 32 + lane];
    const int e0 = g_off[node];
    const int e1 = g_off[node + 1];
    for (int e = e0; e < e1; e++) {
        float4 v = x4[(size_t)g_ssrc[e] * 32 + lane];
        acc.x += v.x; acc.y += v.y; acc.z += v.z; acc.w += v.w;
    }
    uint2 o;
    o.x = pkh(acc.x, acc.y);
    o.y = pkh(acc.z, acc.w);
    reinterpret_cast<uint2*>(agg)[(size_t)node * 32 + lane] = o;
}

// ---------------------------------------------------------------------------
// Aggregation layer 2: fp16 h in, fp16 agg out. Warp per node; lane holds
// one uint4 = 8 halves (HID=256 -> 32 uint4/row). fp32 accumulation.
// ---------------------------------------------------------------------------
__global__ void agg2_kernel(const __half* __restrict__ h,
                            __half* __restrict__ agg) {
    const int node = blockIdx.x * 8 + (threadIdx.x >> 5);
    if (node >= N_NODES) return;
    const int lane = threadIdx.x & 31;
    const uint4* h4 = reinterpret_cast<const uint4*>(h);

    uint4 sv = h4[(size_t)node * 32 + lane];
    float2 a0 = h2f(sv.x), a1 = h2f(sv.y), a2 = h2f(sv.z), a3 = h2f(sv.w);
    const int e0 = g_off[node];
    const int e1 = g_off[node + 1];
    for (int e = e0; e < e1; e++) {
        uint4 v = h4[(size_t)g_ssrc[e] * 32 + lane];
        float2 b0 = h2f(v.x), b1 = h2f(v.y), b2 = h2f(v.z), b3 = h2f(v.w);
        a0.x += b0.x; a0.y += b0.y;
        a1.x += b1.x; a1.y += b1.y;
        a2.x += b2.x; a2.y += b2.y;
        a3.x += b3.x; a3.y += b3.y;
    }
    uint4 o;
    o.x = pkh(a0.x, a0.y);
    o.y = pkh(a1.x, a1.y);
    o.z = pkh(a2.x, a2.y);
    o.w = pkh(a3.x, a3.y);
    reinterpret_cast<uint4*>(agg)[(size_t)node * 32 + lane] = o;
}

// ---------------------------------------------------------------------------
// fp16 mma.sync GEMM, full-width tile, all-cp.async staging:
// C[M,256] = relu(A[M,K] @ W[K,256] + bias), A fp16 in gmem.
// CTA 128x256, 512 threads (16 warps 4m x 4n), warp tile 32x64, BK=32,
// 2 stages. SMEM/stage: A[128 rows][80B] | B[32 k-rows][528B]
// HOUT: write __half output (h1/h) vs float (z).
// ---------------------------------------------------------------------------
#define A_OFF 0
#define B_OFF 10240                    // 128*80
#define STAGE_BYTES 27136              // B_OFF + 32*528
#define SMEM_MMA_BYTES (2 * STAGE_BYTES)

template <int NC, bool HOUT>  // NC = K/32
__global__ __launch_bounds__(512)
void gemm_mma(const __half* __restrict__ A, const __half* __restrict__ wp,
              const float* __restrict__ bias, void* __restrict__ Cv, int M) {
    extern __shared__ __align__(1024) char smem[];
    const uint32_t sb = smem_u32(smem);
    const int K = NC * 32;
    const int t = threadIdx.x;
    const int lane = t & 31;
    const int warp = t >> 5;
    const int warp_m = warp >> 2;  // 0..3 (32 rows each)
    const int warp_n = warp & 3;   // 0..3 (64 cols each)
    const int bm = blockIdx.x * 128;

    // ---- A fill coords: 128 rows x 4 x 16B chunks = 512, 1 per thread ----
    const int a_row = t >> 2;
    const int a_seg = t & 3;
    const int a_node = min(bm + a_row, M - 1);  // clamp: OOB rows unused
    const __half* Ag = A + (size_t)a_node * K + a_seg * 8;
    const uint32_t a_dst = sb + a_row * 80 + a_seg * 16;

    // ---- ldmatrix per-thread offsets ----
    const int lm_arow = warp_m * 32 + (lane & 7) + ((lane >> 3) & 1) * 8;
    const uint32_t a_lm = sb + lm_arow * 80 + ((lane >> 4) & 1) * 16;
    const uint32_t b_lm = sb + B_OFF + (lane & 15) * 528 + warp_n * 128;

    float acc[2][8][4];
#pragma unroll
    for (int i = 0; i < 2; i++)
#pragma unroll
        for (int j = 0; j < 8; j++)
#pragma unroll
            for (int k = 0; k < 4; k++) acc[i][j][k] = 0.f;

    // ---- combined A+B fill for chunk c into stage stg ----
    auto fill_AB = [&](int c, int stg) {
        CP_ASYNC16(a_dst + stg * STAGE_BYTES, (const void*)(Ag + c * 32));
#pragma unroll
        for (int i = 0; i < 2; i++) {
            int f = t + i * 512;
            int k = (f >> 5) & 31;
            int seg = f & 31;
            const __half* src = wp + ((size_t)c * 32 + k) * 256 + seg * 8;
            uint32_t dst =
                sb + stg * STAGE_BYTES + B_OFF + k * 528 + seg * 16;
            CP_ASYNC16(dst, (const void*)src);
        }
        CP_COMMIT();
    };
    auto compute = [&](int stg) {
        const uint32_t abase = a_lm + stg * STAGE_BYTES;
        const uint32_t bbase = b_lm + stg * STAGE_BYTES;
#pragma unroll
        for (int ks = 0; ks < 2; ks++) {
            uint32_t Ah[2][4], Bh[8][2];
#pragma unroll
            for (int mt = 0; mt < 2; mt++)
                LDSM4(Ah[mt], abase + mt * (16 * 80) + ks * 32);
#pragma unroll
            for (int nt = 0; nt < 8; nt++)
                LDSM2T(Bh[nt], bbase + ks * (16 * 528) + nt * 16);
#pragma unroll
            for (int mt = 0; mt < 2; mt++)
#pragma unroll
                for (int nt = 0; nt < 8; nt++)
                    MMA16816F(acc[mt][nt], Ah[mt], Bh[nt]);
        }
    };

    // ---- prologue ----
    fill_AB(0, 0);
    CP_WAIT0();
    __syncthreads();
    // ---- main loop ----
    for (int c = 0; c < NC; c++) {
        const int s = c & 1;
        const bool nxt = (c + 1 < NC);
        if (nxt) fill_AB(c + 1, s ^ 1);
        compute(s);
        if (nxt) {
            CP_WAIT0();
            __syncthreads();
        }
    }

    // ---- epilogue: bias + relu ----
#pragma unroll
    for (int mt = 0; mt < 2; mt++) {
        int r0 = bm + warp_m * 32 + mt * 16 + (lane >> 2);
#pragma unroll
        for (int nt = 0; nt < 8; nt++) {
            int col = warp_n * 64 + nt * 8 + (lane & 3) * 2;
            float b0 = bias[col], b1 = bias[col + 1];
            float o0 = fmaxf(acc[mt][nt][0] + b0, 0.f);
            float o1 = fmaxf(acc[mt][nt][1] + b1, 0.f);
            float o2 = fmaxf(acc[mt][nt][2] + b0, 0.f);
            float o3 = fmaxf(acc[mt][nt][3] + b1, 0.f);
            if (HOUT) {
                __half* C = (__half*)Cv;
                if (r0 < M)
                    *reinterpret_cast<uint32_t*>(C + (size_t)r0 * HID + col) =
                        pkh(o0, o1);
                if (r0 + 8 < M)
                    *reinterpret_cast<uint32_t*>(C + (size_t)(r0 + 8) * HID +
                                                 col) = pkh(o2, o3);
            } else {
                float* C = (float*)Cv;
                if (r0 < M)
                    *reinterpret_cast<float2*>(C + (size_t)r0 * HID + col) =
                        make_float2(o0, o1);
                if (r0 + 8 < M)
                    *reinterpret_cast<float2*>(C + (size_t)(r0 + 8) * HID +
                                               col) = make_float2(o2, o3);
            }
        }
    }
}

// ---------------------------------------------------------------------------
// Final GEMM: out[M,10] = Z[M,256] @ W[256,10] + b. (fp32)
// ---------------------------------------------------------------------------
__global__ void gemm_out_k(const float* __restrict__ Z,
                           const float* __restrict__ W,
                           const float* __restrict__ bias,
                           float* __restrict__ out) {
    __shared__ float Ws[NCLS][HID];
    __shared__ float bs[NCLS];
    const int t = threadIdx.x;
    for (int i = t; i < HID * NCLS; i += 256) {
        int k = i / NCLS;
        int c = i - k * NCLS;
        Ws[c][k] = W[i];
    }
    if (t < NCLS) bs[t] = bias[t];
    __syncthreads();

    const int lane = t & 31;
    const int row = blockIdx.x * 8 + (t >> 5);
    if (row >= N_NODES) return;

    const float* zr = Z + (size_t)row * HID;
    float zv[8];
#pragma unroll
    for (int i = 0; i < 8; i++) zv[i] = zr[i * 32 + lane];

#pragma unroll
    for (int c = 0; c < NCLS; c++) {
        float s = 0.f;
#pragma unroll
        for (int i = 0; i < 8; i++) s += zv[i] * Ws[c][i * 32 + lane];
#pragma unroll
        for (int o = 16; o > 0; o >>= 1) s += __shfl_xor_sync(0xffffffffu, s, o);
        if (lane == 0) out[row * NCLS + c] = s + bs[c];
    }
}

// ---------------------------------------------------------------------------
// Launch sequence (default stream; graph-capturable, alloc-free)
// ---------------------------------------------------------------------------
extern "C" void kernel_launch(void* const* d_in, const int* in_sizes, int n_in,
                              void* d_out, int out_size) {
    (void)in_sizes; (void)n_in; (void)out_size;
    const float* x = (const float*)d_in[0];
    const void* ei = d_in[1];
    const float* W1a = (const float*)d_in[2];
    const float* b1a = (const float*)d_in[3];
    const float* W1b = (const float*)d_in[4];
    const float* b1b = (const float*)d_in[5];
    const float* W2a = (const float*)d_in[6];
    const float* b2a = (const float*)d_in[7];
    const float* W2b = (const float*)d_in[8];
    const float* b2b = (const float*)d_in[9];
    float* out = (float*)d_out;

    __half *agg1, *h1, *h, *agg2, *wp1, *wp2, *wp3;
    float* z;
    cudaGetSymbolAddress((void**)&agg1, g_agg1);
    cudaGetSymbolAddress((void**)&h1, g_h1);
    cudaGetSymbolAddress((void**)&h, g_h);
    cudaGetSymbolAddress((void**)&agg2, g_agg2);
    cudaGetSymbolAddress((void**)&z, g_z);
    cudaGetSymbolAddress((void**)&wp1, g_wp1);
    cudaGetSymbolAddress((void**)&wp2, g_wp2);
    cudaGetSymbolAddress((void**)&wp3, g_wp3);

    cudaFuncSetAttribute(gemm_mma<4, true>,
                         cudaFuncAttributeMaxDynamicSharedMemorySize,
                         SMEM_MMA_BYTES);
    cudaFuncSetAttribute(gemm_mma<8, true>,
                         cudaFuncAttributeMaxDynamicSharedMemorySize,
                         SMEM_MMA_BYTES);
    cudaFuncSetAttribute(gemm_mma<8, false>,
                         cudaFuncAttributeMaxDynamicSharedMemorySize,
                         SMEM_MMA_BYTES);

    // ---- setup + CSR build ----
    const int scan_blocks = (N_NODES + 1023) / 1024;  // 98
    setup_kernel<<<(N_NODES + 255) / 256, 256>>>(W1a, W1b, W2a);
    convert_hist_kernel<<<(N_EDGES + 255) / 256, 256>>>(ei);
    scan1_kernel<<<scan_blocks, 1024>>>();
    scan2_kernel<<<1, 128>>>(scan_blocks);
    scan3_kernel<<<scan_blocks, 1024>>>();
    scatter_kernel<<<(N_EDGES + 255) / 256, 256>>>();

    const int tg = (N_NODES + 127) / 128;  // 782 full-width tiles
    const int agg_blocks = (N_NODES + 7) / 8;

    // ---- layer 1 ----
    agg1_kernel<<<agg_blocks, 256>>>(x, agg1);
    gemm_mma<4, true><<<tg, 512, SMEM_MMA_BYTES>>>(agg1, wp1, b1a, h1,
                                                   N_NODES);
    gemm_mma<8, true><<<tg, 512, SMEM_MMA_BYTES>>>(h1, wp2, b1b, h, N_NODES);
    // ---- layer 2 ----
    agg2_kernel<<<agg_blocks, 256>>>(h, agg2);
    gemm_mma<8, false><<<tg, 512, SMEM_MMA_BYTES>>>(agg2, wp3, b2a, z,
                                                    N_NODES);
    gemm_out_k<<<(N_NODES + 7) / 8, 256>>>(z, W2b, b2b, out);
}

// round 17
// speedup vs baseline: 2.0538x; 1.0895x over previous
#include <cuda_runtime.h>
#include <cuda_fp16.h>
#include <cstdint>

#define N_NODES 100000
#define N_EDGES 640000
#define FEAT 128
#define HID 256
#define NCLS 10

// ---------------------------------------------------------------------------
// Persistent scratch (re-initialized every launch before use).
// ---------------------------------------------------------------------------
__device__ __align__(16) __half g_xq[N_NODES * FEAT];   // x quantized fp16
__device__ __align__(16) __half g_agg1[N_NODES * FEAT];
__device__ __align__(16) __half g_h1[N_NODES * HID];
__device__ __align__(16) __half g_h[N_NODES * HID];
__device__ __align__(16) __half g_agg2[N_NODES * HID];
__device__ int g_src[N_EDGES];
__device__ int g_dst[N_EDGES];
__device__ int g_ssrc[N_EDGES];     // src sorted by dst
__device__ int g_cnt[N_NODES];
__device__ int g_off[N_NODES + 1];
__device__ int g_cur[N_NODES];
__device__ int g_bsum[128];         // scan block sums
// prepped weights, fp16 row-major [k][n(256)]
__device__ __align__(16) __half g_wp1[128 * 256];  // W1a
__device__ __align__(16) __half g_wp2[256 * 256];  // W1b
__device__ __align__(16) __half g_wp3[256 * 256];  // W2a

// ---------------------------------------------------------------------------
// mma.sync helpers (legacy tensor-core path; valid at compute_100)
// ---------------------------------------------------------------------------
#define LDSM4(r, a)                                                           \
    asm volatile("ldmatrix.sync.aligned.m8n8.x4.shared.b16 {%0,%1,%2,%3}, [%4];" \
                 : "=r"((r)[0]), "=r"((r)[1]), "=r"((r)[2]), "=r"((r)[3])     \
                 : "r"(a))
#define LDSM2T(r, a)                                                          \
    asm volatile("ldmatrix.sync.aligned.m8n8.x2.trans.shared.b16 {%0,%1}, [%2];" \
                 : "=r"((r)[0]), "=r"((r)[1])                                 \
                 : "r"(a))
#define MMA16816F(c, A, B)                                                    \
    asm volatile(                                                             \
        "mma.sync.aligned.m16n8k16.row.col.f32.f16.f16.f32 "                  \
        "{%0,%1,%2,%3},{%4,%5,%6,%7},{%8,%9},{%0,%1,%2,%3};"                  \
        : "+f"((c)[0]), "+f"((c)[1]), "+f"((c)[2]), "+f"((c)[3])              \
        : "r"((A)[0]), "r"((A)[1]), "r"((A)[2]), "r"((A)[3]), "r"((B)[0]),    \
          "r"((B)[1]))
#define CP_ASYNC16(dst, src)                                                  \
    asm volatile("cp.async.cg.shared.global [%0], [%1], 16;" ::"r"(dst),      \
                 "l"(src) : "memory")
#define CP_COMMIT() asm volatile("cp.async.commit_group;" ::: "memory")
#define CP_WAIT0() asm volatile("cp.async.wait_group 0;" ::: "memory")

__device__ __forceinline__ uint32_t smem_u32(const void* p) {
    uint32_t a;
    asm("{ .reg .u64 t; cvta.to.shared.u64 t, %1; cvt.u32.u64 %0, t; }"
        : "=r"(a) : "l"(p));
    return a;
}
__device__ __forceinline__ uint32_t pkh(float lo, float hi) {
    __half2 h = __floats2half2_rn(lo, hi);
    return *reinterpret_cast<uint32_t*>(&h);
}
__device__ __forceinline__ float2 h2f(uint32_t u) {
    __half2 h = *reinterpret_cast<__half2*>(&u);
    return __half22float2(h);
}

// ---------------------------------------------------------------------------
// Fused setup: weight prep (fp32 -> fp16 row-major) + zero histogram bins.
// ---------------------------------------------------------------------------
__global__ void setup_kernel(const float* __restrict__ W1a,
                             const float* __restrict__ W1b,
                             const float* __restrict__ W2a) {
    int i = blockIdx.x * 256 + threadIdx.x;
    if (i < 128 * 256) g_wp1[i] = __float2half(W1a[i]);
    if (i < 256 * 256) {
        g_wp2[i] = __float2half(W1b[i]);
        g_wp3[i] = __float2half(W2a[i]);
    }
    if (i < N_NODES) g_cnt[i] = 0;
}

// x fp32 -> fp16 (one pass; layer-1 gathers then read half traffic)
__global__ void quantx_kernel(const float* __restrict__ x) {
    int i = blockIdx.x * 256 + threadIdx.x;
    if (i >= N_NODES * FEAT / 4) return;
    float4 v = reinterpret_cast<const float4*>(x)[i];
    uint2 o;
    o.x = pkh(v.x, v.y);
    o.y = pkh(v.z, v.w);
    reinterpret_cast<uint2*>(g_xq)[i] = o;
}

// ---------------------------------------------------------------------------
// Edge-index conversion + histogram with per-block dtype sniff (JAX may
// demote int64->int32): genuine int64 of values < 2^31 has 0 in every odd
// 32-bit word of the first 256 slots; int32 random data cannot (p~1e-1280).
// ---------------------------------------------------------------------------
__global__ void convert_hist_kernel(const void* __restrict__ ei) {
    __shared__ int s_is64;
    if (threadIdx.x == 0) {
        const unsigned int* w = (const unsigned int*)ei;
        int is64 = 1;
        for (int i = 0; i < 256; i++)
            if (w[2 * i + 1] != 0u) { is64 = 0; break; }
        s_is64 = is64;
    }
    __syncthreads();
    int e = blockIdx.x * 256 + threadIdx.x;
    if (e >= N_EDGES) return;
    int s, d;
    if (s_is64) {
        const long long* p = (const long long*)ei;
        s = (int)p[e];
        d = (int)p[N_EDGES + e];
    } else {
        const int* p = (const int*)ei;
        s = p[e];
        d = p[N_EDGES + e];
    }
    s = min(max(s, 0), N_NODES - 1);
    d = min(max(d, 0), N_NODES - 1);
    g_src[e] = s;
    g_dst[e] = d;
    atomicAdd(&g_cnt[d], 1);
}

// scan step 1: per-block (1024 elems) exclusive scan + block sums
__global__ void scan1_kernel() {
    __shared__ int sh[1024];
    const int tid = threadIdx.x;
    int i = blockIdx.x * 1024 + tid;
    int v = (i < N_NODES) ? g_cnt[i] : 0;
    sh[tid] = v;
    __syncthreads();
#pragma unroll
    for (int o = 1; o < 1024; o <<= 1) {
        int t = (tid >= o) ? sh[tid - o] : 0;
        __syncthreads();
        sh[tid] += t;
        __syncthreads();
    }
    if (i < N_NODES) g_off[i] = sh[tid] - v;
    if (tid == 1023) g_bsum[blockIdx.x] = sh[1023];
}

// scan step 2: exclusive scan over block sums (<=128 entries), one block
__global__ void scan2_kernel(int nb) {
    __shared__ int sh[128];
    const int tid = threadIdx.x;
    int v = (tid < nb) ? g_bsum[tid] : 0;
    sh[tid] = v;
    __syncthreads();
#pragma unroll
    for (int o = 1; o < 128; o <<= 1) {
        int t = (tid >= o) ? sh[tid - o] : 0;
        __syncthreads();
        sh[tid] += t;
        __syncthreads();
    }
    if (tid < nb) g_bsum[tid] = sh[tid] - v;
}

// scan step 3: add block prefix, init cursors, cap sentinel
__global__ void scan3_kernel() {
    int i = blockIdx.x * 1024 + threadIdx.x;
    if (i < N_NODES) {
        int v = g_off[i] + g_bsum[blockIdx.x];
        g_off[i] = v;
        g_cur[i] = v;
    }
    if (i == 0) g_off[N_NODES] = N_EDGES;
}

__global__ void scatter_kernel() {
    int e = blockIdx.x * 256 + threadIdx.x;
    if (e >= N_EDGES) return;
    int d = g_dst[e];
    int pos = atomicAdd(&g_cur[d], 1);
    g_ssrc[pos] = g_src[e];
}

// ---------------------------------------------------------------------------
// Aggregation, fp16 in / fp16 out, fp32 accumulate. Warp per node.
// D=128: lane holds uint2 (4 halves); D=256: lane holds uint4 (8 halves).
// ---------------------------------------------------------------------------
__global__ void agg1_kernel(const __half* __restrict__ xin,
                            __half* __restrict__ agg) {
    const int node = blockIdx.x * 8 + (threadIdx.x >> 5);
    if (node >= N_NODES) return;
    const int lane = threadIdx.x & 31;
    const uint2* h2p = reinterpret_cast<const uint2*>(xin);

    uint2 sv = h2p[(size_t)node * 32 + lane];
    float2 a0 = h2f(sv.x), a1 = h2f(sv.y);
    const int e0 = g_off[node];
    const int e1 = g_off[node + 1];
    for (int e = e0; e < e1; e++) {
        uint2 v = h2p[(size_t)g_ssrc[e] * 32 + lane];
        float2 b0 = h2f(v.x), b1 = h2f(v.y);
        a0.x += b0.x; a0.y += b0.y;
        a1.x += b1.x; a1.y += b1.y;
    }
    uint2 o;
    o.x = pkh(a0.x, a0.y);
    o.y = pkh(a1.x, a1.y);
    reinterpret_cast<uint2*>(agg)[(size_t)node * 32 + lane] = o;
}

__global__ void agg2_kernel(const __half* __restrict__ h,
                            __half* __restrict__ agg) {
    const int node = blockIdx.x * 8 + (threadIdx.x >> 5);
    if (node >= N_NODES) return;
    const int lane = threadIdx.x & 31;
    const uint4* h4 = reinterpret_cast<const uint4*>(h);

    uint4 sv = h4[(size_t)node * 32 + lane];
    float2 a0 = h2f(sv.x), a1 = h2f(sv.y), a2 = h2f(sv.z), a3 = h2f(sv.w);
    const int e0 = g_off[node];
    const int e1 = g_off[node + 1];
    for (int e = e0; e < e1; e++) {
        uint4 v = h4[(size_t)g_ssrc[e] * 32 + lane];
        float2 b0 = h2f(v.x), b1 = h2f(v.y), b2 = h2f(v.z), b3 = h2f(v.w);
        a0.x += b0.x; a0.y += b0.y;
        a1.x += b1.x; a1.y += b1.y;
        a2.x += b2.x; a2.y += b2.y;
        a3.x += b3.x; a3.y += b3.y;
    }
    uint4 o;
    o.x = pkh(a0.x, a0.y);
    o.y = pkh(a1.x, a1.y);
    o.z = pkh(a2.x, a2.y);
    o.w = pkh(a3.x, a3.y);
    reinterpret_cast<uint4*>(agg)[(size_t)node * 32 + lane] = o;
}

// ---------------------------------------------------------------------------
// fp16 mma.sync GEMM, full-width tile, all-cp.async staging:
// tile = relu(A[M,K] @ W[K,256] + bias)
// MODE 0: write tile as fp16 to Cv.
// MODE 1: fuse final layer: out[M,10] = tile @ W2b + b2b (smem reduction),
//         Cv = out (fp32). W2b cached in smem, partials via smem atomicAdd.
// CTA 128x256, 512 threads (16 warps 4m x 4n), warp tile 32x64, BK=32.
// SMEM: 2 stages (A[128][80B] | B[32][528B]) then out_tile + W2b (MODE 1).
// ---------------------------------------------------------------------------
#define A_OFF 0
#define B_OFF 10240                     // 128*80
#define STAGE_BYTES 27136               // B_OFF + 32*528
#define OT_OFF (2 * STAGE_BYTES)        // out_tile: 128*10 fp32 = 5120
#define W2S_OFF (OT_OFF + 5120)         // W2b smem: 256*10 fp32 = 10240
#define SMEM_MMA_BYTES (2 * STAGE_BYTES)
#define SMEM_MMA_OUT_BYTES (W2S_OFF + 10240)

template <int NC, int MODE>  // NC = K/32
__global__ __launch_bounds__(512)
void gemm_mma(const __half* __restrict__ A, const __half* __restrict__ wp,
              const float* __restrict__ bias, void* __restrict__ Cv, int M,
              const float* __restrict__ W2b, const float* __restrict__ b2b) {
    extern __shared__ __align__(1024) char smem[];
    const uint32_t sb = smem_u32(smem);
    const int K = NC * 32;
    const int t = threadIdx.x;
    const int lane = t & 31;
    const int warp = t >> 5;
    const int warp_m = warp >> 2;  // 0..3 (32 rows each)
    const int warp_n = warp & 3;   // 0..3 (64 cols each)
    const int bm = blockIdx.x * 128;

    float* out_tile = reinterpret_cast<float*>(smem + OT_OFF);
    float* W2s = reinterpret_cast<float*>(smem + W2S_OFF);
    if (MODE == 1) {
        for (int i = t; i < 1280; i += 512) out_tile[i] = 0.f;
        for (int i = t; i < HID * NCLS; i += 512) W2s[i] = W2b[i];
    }

    // ---- A fill coords: 128 rows x 4 x 16B chunks = 512, 1 per thread ----
    const int a_row = t >> 2;
    const int a_seg = t & 3;
    const int a_node = min(bm + a_row, M - 1);  // clamp: OOB rows unused
    const __half* Ag = A + (size_t)a_node * K + a_seg * 8;
    const uint32_t a_dst = sb + a_row * 80 + a_seg * 16;

    // ---- ldmatrix per-thread offsets ----
    const int lm_arow = warp_m * 32 + (lane & 7) + ((lane >> 3) & 1) * 8;
    const uint32_t a_lm = sb + lm_arow * 80 + ((lane >> 4) & 1) * 16;
    const uint32_t b_lm = sb + B_OFF + (lane & 15) * 528 + warp_n * 128;

    float acc[2][8][4];
#pragma unroll
    for (int i = 0; i < 2; i++)
#pragma unroll
        for (int j = 0; j < 8; j++)
#pragma unroll
            for (int k = 0; k < 4; k++) acc[i][j][k] = 0.f;

    auto fill_AB = [&](int c, int stg) {
        CP_ASYNC16(a_dst + stg * STAGE_BYTES, (const void*)(Ag + c * 32));
#pragma unroll
        for (int i = 0; i < 2; i++) {
            int f = t + i * 512;
            int k = (f >> 5) & 31;
            int seg = f & 31;
            const __half* src = wp + ((size_t)c * 32 + k) * 256 + seg * 8;
            uint32_t dst =
                sb + stg * STAGE_BYTES + B_OFF + k * 528 + seg * 16;
            CP_ASYNC16(dst, (const void*)src);
        }
        CP_COMMIT();
    };
    auto compute = [&](int stg) {
        const uint32_t abase = a_lm + stg * STAGE_BYTES;
        const uint32_t bbase = b_lm + stg * STAGE_BYTES;
#pragma unroll
        for (int ks = 0; ks < 2; ks++) {
            uint32_t Ah[2][4], Bh[8][2];
#pragma unroll
            for (int mt = 0; mt < 2; mt++)
                LDSM4(Ah[mt], abase + mt * (16 * 80) + ks * 32);
#pragma unroll
            for (int nt = 0; nt < 8; nt++)
                LDSM2T(Bh[nt], bbase + ks * (16 * 528) + nt * 16);
#pragma unroll
            for (int mt = 0; mt < 2; mt++)
#pragma unroll
                for (int nt = 0; nt < 8; nt++)
                    MMA16816F(acc[mt][nt], Ah[mt], Bh[nt]);
        }
    };

    // ---- prologue ----
    fill_AB(0, 0);
    CP_WAIT0();
    __syncthreads();
    // ---- main loop ----
    for (int c = 0; c < NC; c++) {
        const int s = c & 1;
        const bool nxt = (c + 1 < NC);
        if (nxt) fill_AB(c + 1, s ^ 1);
        compute(s);
        if (nxt) {
            CP_WAIT0();
            __syncthreads();
        }
    }

    // ---- epilogue ----
#pragma unroll
    for (int mt = 0; mt < 2; mt++) {
        int lr = warp_m * 32 + mt * 16 + (lane >> 2);
        int r0 = bm + lr;
        float pa[NCLS], pb[NCLS];
        if (MODE == 1) {
#pragma unroll
            for (int c2 = 0; c2 < NCLS; c2++) { pa[c2] = 0.f; pb[c2] = 0.f; }
        }
#pragma unroll
        for (int nt = 0; nt < 8; nt++) {
            int col = warp_n * 64 + nt * 8 + (lane & 3) * 2;
            float b0 = bias[col], b1 = bias[col + 1];
            float o0 = fmaxf(acc[mt][nt][0] + b0, 0.f);
            float o1 = fmaxf(acc[mt][nt][1] + b1, 0.f);
            float o2 = fmaxf(acc[mt][nt][2] + b0, 0.f);
            float o3 = fmaxf(acc[mt][nt][3] + b1, 0.f);
            if (MODE == 0) {
                __half* C = (__half*)Cv;
                if (r0 < M)
                    *reinterpret_cast<uint32_t*>(C + (size_t)r0 * HID + col) =
                        pkh(o0, o1);
                if (r0 + 8 < M)
                    *reinterpret_cast<uint32_t*>(C + (size_t)(r0 + 8) * HID +
                                                 col) = pkh(o2, o3);
            } else {
                const float* w0 = W2s + col * NCLS;
                const float* w1 = W2s + (col + 1) * NCLS;
#pragma unroll
                for (int c2 = 0; c2 < NCLS; c2++) {
                    pa[c2] += o0 * w0[c2] + o1 * w1[c2];
                    pb[c2] += o2 * w0[c2] + o3 * w1[c2];
                }
            }
        }
        if (MODE == 1) {
            if (r0 < M) {
#pragma unroll
                for (int c2 = 0; c2 < NCLS; c2++)
                    atomicAdd(&out_tile[lr * NCLS + c2], pa[c2]);
            }
            if (r0 + 8 < M) {
#pragma unroll
                for (int c2 = 0; c2 < NCLS; c2++)
                    atomicAdd(&out_tile[(lr + 8) * NCLS + c2], pb[c2]);
            }
        }
    }
    if (MODE == 1) {
        __syncthreads();
        float* out = (float*)Cv;
        for (int i = t; i < 128 * NCLS; i += 512) {
            int r = i / NCLS;
            int c2 = i - r * NCLS;
            if (bm + r < M)
                out[(size_t)(bm + r) * NCLS + c2] = out_tile[i] + b2b[c2];
        }
    }
}

// ---------------------------------------------------------------------------
// Launch sequence (default stream; graph-capturable, alloc-free)
// ---------------------------------------------------------------------------
extern "C" void kernel_launch(void* const* d_in, const int* in_sizes, int n_in,
                              void* d_out, int out_size) {
    (void)in_sizes; (void)n_in; (void)out_size;
    const float* x = (const float*)d_in[0];
    const void* ei = d_in[1];
    const float* W1a = (const float*)d_in[2];
    const float* b1a = (const float*)d_in[3];
    const float* W1b = (const float*)d_in[4];
    const float* b1b = (const float*)d_in[5];
    const float* W2a = (const float*)d_in[6];
    const float* b2a = (const float*)d_in[7];
    const float* W2b = (const float*)d_in[8];
    const float* b2b = (const float*)d_in[9];
    float* out = (float*)d_out;

    __half *xq, *agg1, *h1, *h, *agg2, *wp1, *wp2, *wp3;
    cudaGetSymbolAddress((void**)&xq, g_xq);
    cudaGetSymbolAddress((void**)&agg1, g_agg1);
    cudaGetSymbolAddress((void**)&h1, g_h1);
    cudaGetSymbolAddress((void**)&h, g_h);
    cudaGetSymbolAddress((void**)&agg2, g_agg2);
    cudaGetSymbolAddress((void**)&wp1, g_wp1);
    cudaGetSymbolAddress((void**)&wp2, g_wp2);
    cudaGetSymbolAddress((void**)&wp3, g_wp3);

    cudaFuncSetAttribute(gemm_mma<4, 0>,
                         cudaFuncAttributeMaxDynamicSharedMemorySize,
                         SMEM_MMA_BYTES);
    cudaFuncSetAttribute(gemm_mma<8, 0>,
                         cudaFuncAttributeMaxDynamicSharedMemorySize,
                         SMEM_MMA_BYTES);
    cudaFuncSetAttribute(gemm_mma<8, 1>,
                         cudaFuncAttributeMaxDynamicSharedMemorySize,
                         SMEM_MMA_OUT_BYTES);

    // ---- setup + CSR build ----
    const int scan_blocks = (N_NODES + 1023) / 1024;  // 98
    setup_kernel<<<(N_NODES + 255) / 256, 256>>>(W1a, W1b, W2a);
    quantx_kernel<<<(N_NODES * FEAT / 4 + 255) / 256, 256>>>(x);
    convert_hist_kernel<<<(N_EDGES + 255) / 256, 256>>>(ei);
    scan1_kernel<<<scan_blocks, 1024>>>();
    scan2_kernel<<<1, 128>>>(scan_blocks);
    scan3_kernel<<<scan_blocks, 1024>>>();
    scatter_kernel<<<(N_EDGES + 255) / 256, 256>>>();

    const int tg = (N_NODES + 127) / 128;  // 782 full-width tiles
    const int agg_blocks = (N_NODES + 7) / 8;

    // ---- layer 1 ----
    agg1_kernel<<<agg_blocks, 256>>>(xq, agg1);
    gemm_mma<4, 0><<<tg, 512, SMEM_MMA_BYTES>>>(agg1, wp1, b1a, h1, N_NODES,
                                                nullptr, nullptr);
    gemm_mma<8, 0><<<tg, 512, SMEM_MMA_BYTES>>>(h1, wp2, b1b, h, N_NODES,
                                                nullptr, nullptr);
    // ---- layer 2 (final GEMM fused into gemm3 epilogue) ----
    agg2_kernel<<<agg_blocks, 256>>>(h, agg2);
    gemm_mma<8, 1><<<tg, 512, SMEM_MMA_OUT_BYTES>>>(agg2, wp3, b2a, out,
                                                    N_NODES, W2b, b2b);
}